// round 12
// baseline (speedup 1.0000x reference)
#include <cuda_runtime.h>
#include <cuda_fp16.h>
#include <math.h>
#include <stdint.h>

// x: (4,192,256,256) fp32, WS=8, shift=4, NHEADS=4, HD=48, nW=4096, T=64
// 384 threads (12 warps), 1 window/CTA. fp16 mma.sync m16n8k16 (10-bit mantissa
// = tf32 precision, 2x MACs/inst). Activations half (stride 200: word stride
// 100 = 4 mod 32, conflict-free half2 frags). Weights pre-converted+transposed
// to fp16 scratch wT[col][k] by a helper kernel; warp-private 4-deep cp.async
// rings ([col][k] tiles, stride 24 halves). fp32 accumulate + fp32 LN/softmax.
#define SAH 200        // half stride of activation buffers
#define SPF 68         // float stride of fp32 scores P
#define SPH 72         // half stride of fp16 probs PH
#define STH 24         // half stride per col of staged weight tile
#define HX 0           // X residual (LN1 out), 64x200 halves
#define HQ 12800       // Q -> O concat
#define HK 25600       // K -> H (LN2 out)
#define HV 38400       // V -> G (gelu out)
#define PF_OFF 25600   // float index of P region (byte 102400), 4352 f
#define PH_OFF 59904   // half index of PH (byte 119808), 4608 h
#define RING_OFF 64512 // half index of rings (byte 129024): warp w +w*3072, buf b +b*768
#define SMEM_BYTES 202752

// fp16 transposed weight scratch: qkv[576][192] | wo[192][192] | wm1[768][192] | wm2[192][768]
#define WT_QKV 0
#define WT_O   110592
#define WT_M1  147456
#define WT_M2  294912
#define WT_TOTAL 442368
static __device__ __align__(16) __half g_wT[WT_TOTAL];

__global__ void cvt_weights(const float* __restrict__ wqkv, const float* __restrict__ wo,
                            const float* __restrict__ wm1,  const float* __restrict__ wm2)
{
    const int idx = blockIdx.x * 256 + threadIdx.x;
    if (idx >= WT_TOTAL) return;
    float v;
    if (idx < WT_O) {                 // qkv: wT[col][k], col<576, k<192
        const int col = idx / 192, k = idx - col * 192;
        v = wqkv[k * 576 + col];
    } else if (idx < WT_M1) {         // wo: col<192, k<192
        const int i = idx - WT_O, col = i / 192, k = i - col * 192;
        v = wo[k * 192 + col];
    } else if (idx < WT_M2) {         // wm1: col<768, k<192
        const int i = idx - WT_M1, col = i / 192, k = i - col * 192;
        v = wm1[k * 768 + col];
    } else {                          // wm2: col<192, k<768
        const int i = idx - WT_M2, col = i / 768, k = i - col * 768;
        v = wm2[k * 192 + col];
    }
    g_wT[idx] = __float2half_rn(v);
}

__device__ __forceinline__ void mma_f16(float (&d)[4],
                                        uint32_t a0, uint32_t a1, uint32_t a2, uint32_t a3,
                                        uint32_t b0, uint32_t b1)
{
    asm volatile(
        "mma.sync.aligned.m16n8k16.row.col.f32.f16.f16.f32 "
        "{%0,%1,%2,%3}, {%4,%5,%6,%7}, {%8,%9}, {%0,%1,%2,%3};"
        : "+f"(d[0]), "+f"(d[1]), "+f"(d[2]), "+f"(d[3])
        : "r"(a0), "r"(a1), "r"(a2), "r"(a3), "r"(b0), "r"(b1));
}

// stage one 32col x 16k fp16 weight tile ([col][k], stride STH) via cp.async
__device__ __forceinline__ void stage_w16(__half* smh, int dstH,
                                          const __half* __restrict__ wT,
                                          int Ktot, int c0g, int k0, int lane)
{
    #pragma unroll
    for (int it = 0; it < 2; it++) {
        const int col  = it * 16 + (lane & 15);
        const int part = lane >> 4;
        const uint32_t dst =
            (uint32_t)__cvta_generic_to_shared(smh + dstH + col * STH + part * 8);
        asm volatile("cp.async.ca.shared.global [%0], [%1], 16;\n"
                     :: "r"(dst),
                        "l"((const void*)(wT + (size_t)(c0g + col) * Ktot + k0 + part * 8)));
    }
}

// acc[2][4][4] += A(64x192 half smem) @ wT[:, col .. col+32); NO CTA barriers
__device__ __forceinline__ void gemm_h(__half* smh, int aH,
                                       const __half* __restrict__ wT,
                                       int Ktot, int colbase,
                                       int lane, int mi, int nj, int ringH,
                                       float (&acc)[2][4][4])
{
    const int gr = lane >> 2, tg = lane & 3;
    const int c0g = colbase + nj * 32;
    stage_w16(smh, ringH + 0 * 768, wT, Ktot, c0g, 0, lane);
    asm volatile("cp.async.commit_group;");
    stage_w16(smh, ringH + 1 * 768, wT, Ktot, c0g, 16, lane);
    asm volatile("cp.async.commit_group;");
    stage_w16(smh, ringH + 2 * 768, wT, Ktot, c0g, 32, lane);
    asm volatile("cp.async.commit_group;");
    #pragma unroll 2
    for (int kt = 0; kt < 12; kt++) {
        if (kt < 9) {
            stage_w16(smh, ringH + ((kt + 3) & 3) * 768, wT, Ktot, c0g, (kt + 3) * 16, lane);
            asm volatile("cp.async.commit_group;");
            asm volatile("cp.async.wait_group 3;");
        } else if (kt == 9)  { asm volatile("cp.async.wait_group 2;"); }
        else if (kt == 10)   { asm volatile("cp.async.wait_group 1;"); }
        else                 { asm volatile("cp.async.wait_group 0;"); }
        __syncwarp();
        const __half* sW = smh + ringH + (kt & 3) * 768;
        uint32_t b0[4], b1[4];
        #pragma unroll
        for (int sn = 0; sn < 4; sn++) {
            const __half* bp_ = sW + (sn * 8 + gr) * STH + tg * 2;
            b0[sn] = *(const uint32_t*)bp_;
            b1[sn] = *(const uint32_t*)(bp_ + 8);
        }
        #pragma unroll
        for (int s = 0; s < 2; s++) {
            const __half* Ab = smh + aH + (mi * 32 + s * 16 + gr) * SAH + kt * 16 + tg * 2;
            const uint32_t a0 = *(const uint32_t*)Ab;
            const uint32_t a1 = *(const uint32_t*)(Ab + 8 * SAH);
            const uint32_t a2 = *(const uint32_t*)(Ab + 8);
            const uint32_t a3 = *(const uint32_t*)(Ab + 8 * SAH + 8);
            #pragma unroll
            for (int sn = 0; sn < 4; sn++)
                mma_f16(acc[s][sn], a0, a1, a2, a3, b0[sn], b1[sn]);
        }
        __syncwarp();
    }
}

// token-parallel LayerNorm on half buffers, fp32 math (sync at entry and exit)
__device__ __forceinline__ void layernorm_h(__half* smh, float* smf,
                                            int srcH, int dstH,
                                            const float* __restrict__ g,
                                            const float* __restrict__ bp, int tid)
{
    __syncthreads();
    const int t = tid & 63, chk = tid >> 6;       // 6 chunks of 32 channels
    {
        const uint4* r4 = (const uint4*)(smh + srcH + t * SAH + chk * 32);
        float s = 0.f, s2 = 0.f;
        #pragma unroll
        for (int j = 0; j < 4; j++) {
            uint4 u = r4[j];
            const uint32_t w[4] = {u.x, u.y, u.z, u.w};
            #pragma unroll
            for (int q = 0; q < 4; q++) {
                const float2 v = __half22float2(*(const half2*)&w[q]);
                s += v.x + v.y; s2 += v.x * v.x + v.y * v.y;
            }
        }
        smf[PF_OFF + chk * 64 + t]       = s;
        smf[PF_OFF + 384 + chk * 64 + t] = s2;
    }
    __syncthreads();
    if (tid < 64) {
        float s = 0.f, s2 = 0.f;
        #pragma unroll
        for (int ch = 0; ch < 6; ch++) {
            s  += smf[PF_OFF + ch * 64 + tid];
            s2 += smf[PF_OFF + 384 + ch * 64 + tid];
        }
        const float mean = s * (1.f / 192.f);
        const float var  = s2 * (1.f / 192.f) - mean * mean;
        smf[PF_OFF + 768 + tid] = mean;
        smf[PF_OFF + 832 + tid] = rsqrtf(var + 1e-5f);
    }
    __syncthreads();
    {
        const float mean = smf[PF_OFF + 768 + t];
        const float rstd = smf[PF_OFF + 832 + t];
        const uint4* r4 = (const uint4*)(smh + srcH + t * SAH + chk * 32);
        uint4* d4 = (uint4*)(smh + dstH + t * SAH + chk * 32);
        #pragma unroll
        for (int j = 0; j < 4; j++) {
            uint4 u = r4[j], o;
            uint32_t* up = (uint32_t*)&u;
            uint32_t* op = (uint32_t*)&o;
            #pragma unroll
            for (int q = 0; q < 4; q++) {
                const int c = chk * 32 + j * 8 + q * 2;
                float2 v = __half22float2(*(const half2*)&up[q]);
                v.x = (v.x - mean) * rstd * __ldg(&g[c])     + __ldg(&bp[c]);
                v.y = (v.y - mean) * rstd * __ldg(&g[c + 1]) + __ldg(&bp[c + 1]);
                *(half2*)&op[q] = __float22half2_rn(v);
            }
            d4[j] = o;
        }
    }
    __syncthreads();
}

__global__ __launch_bounds__(384, 1)
void swin_block_kernel(const float* __restrict__ x,
                       const float* __restrict__ g1,  const float* __restrict__ b1,
                       const float* __restrict__ bqkv,
                       const float* __restrict__ bo,
                       const float* __restrict__ g2,  const float* __restrict__ b2,
                       const float* __restrict__ bm1, const float* __restrict__ bm2,
                       float* __restrict__ out)
{
    extern __shared__ __align__(16) char smraw[];
    __half* smh = (__half*)smraw;
    float*  smf = (float*)smraw;
    const int tid  = threadIdx.x;
    const int wid  = tid >> 5;
    const int lane = tid & 31;
    const int gr   = lane >> 2, tg = lane & 3;
    const int mi   = wid & 1;               // 2 m-tiles of 32 rows
    const int nj   = wid >> 1;              // 6 n-tiles of 32 cols
    const int ringH = RING_OFF + wid * 3072;
    const int wi   = blockIdx.x;
    const int b    = wi >> 10;
    const int hb   = (wi >> 5) & 31;
    const int wb   = wi & 31;

    // ---- gather window into X (half, t-major), shift folded ----
    for (int l = tid; l < 3072; l += 384) {
        const int c    = l >> 4;
        const int r16  = l & 15;
        const int ty   = r16 >> 1, hf = r16 & 1;
        const int sh   = (hb * 8 + ty + 4) & 255;
        const int sw   = (wb * 8 + hf * 4 + 4) & 255;
        const float4 v = *(const float4*)&x[(((size_t)(b * 192 + c)) << 16) + (sh << 8) + sw];
        const int t0 = ty * 8 + hf * 4;
        smh[HX + (t0 + 0) * SAH + c] = __float2half_rn(v.x);
        smh[HX + (t0 + 1) * SAH + c] = __float2half_rn(v.y);
        smh[HX + (t0 + 2) * SAH + c] = __float2half_rn(v.z);
        smh[HX + (t0 + 3) * SAH + c] = __float2half_rn(v.w);
    }

    // ---- LN1 in place (residual base = LN1 output) ----
    layernorm_h(smh, smf, HX, HX, g1, b1, tid);

    // ---- q / k / v GEMMs (warp-private pipelines) ----
    #pragma unroll 1
    for (int p = 0; p < 3; p++) {
        float acc[2][4][4];
        #pragma unroll
        for (int s = 0; s < 2; s++)
            #pragma unroll
            for (int n = 0; n < 4; n++)
                #pragma unroll
                for (int r = 0; r < 4; r++) acc[s][n][r] = 0.f;
        gemm_h(smh, HX, g_wT + WT_QKV, 192, p * 192, lane, mi, nj, ringH, acc);
        __half* dst = smh + ((p == 0) ? HQ : (p == 1) ? HK : HV);
        #pragma unroll
        for (int s = 0; s < 2; s++) {
            const int row = mi * 32 + s * 16 + gr;
            #pragma unroll
            for (int n = 0; n < 4; n++) {
                const int col = nj * 32 + n * 8 + 2 * tg;
                const float bb0 = __ldg(&bqkv[p * 192 + col]);
                const float bb1 = __ldg(&bqkv[p * 192 + col + 1]);
                float2 v0 = {acc[s][n][0] + bb0, acc[s][n][1] + bb1};
                float2 v1 = {acc[s][n][2] + bb0, acc[s][n][3] + bb1};
                *(half2*)(dst + row * SAH + col)       = __float22half2_rn(v0);
                *(half2*)(dst + (row + 8) * SAH + col) = __float22half2_rn(v1);
            }
        }
    }
    __syncthreads();

    // ---- attention per head; O written into Q slab in place ----
    const float scale = 0.14433756729740643f;     // 1/sqrt(48)
    for (int h = 0; h < 4; h++) {
        // scores: S = Q_h @ K_h^T   (both t-major half; 3 k16 steps over 48 ch)
        for (int t = wid; t < 32; t += 12) {
            const int mi2 = t >> 3, ni = t & 7;
            float sc[4] = {0.f, 0.f, 0.f, 0.f};
            const __half* Ab0 = smh + HQ + (mi2 * 16 + gr) * SAH + h * 48 + tg * 2;
            const __half* Bb0 = smh + HK + (ni * 8 + gr) * SAH + h * 48 + tg * 2;
            #pragma unroll
            for (int kk = 0; kk < 3; kk++) {
                const uint32_t a0 = *(const uint32_t*)(Ab0 + kk * 16);
                const uint32_t a1 = *(const uint32_t*)(Ab0 + kk * 16 + 8 * SAH);
                const uint32_t a2 = *(const uint32_t*)(Ab0 + kk * 16 + 8);
                const uint32_t a3 = *(const uint32_t*)(Ab0 + kk * 16 + 8 * SAH + 8);
                const uint32_t b0 = *(const uint32_t*)(Bb0 + kk * 16);
                const uint32_t b1 = *(const uint32_t*)(Bb0 + kk * 16 + 8);
                mma_f16(sc, a0, a1, a2, a3, b0, b1);
            }
            const int row = mi2 * 16 + gr, col = ni * 8 + 2 * tg;
            smf[PF_OFF + row * SPF + col]           = sc[0] * scale;
            smf[PF_OFF + row * SPF + col + 1]       = sc[1] * scale;
            smf[PF_OFF + (row + 8) * SPF + col]     = sc[2] * scale;
            smf[PF_OFF + (row + 8) * SPF + col + 1] = sc[3] * scale;
        }
        __syncthreads();

        if (tid < 256) {          // softmax (fp32) + write fp16 probs to PH
            const int t = tid >> 2, qd = tid & 3;
            float* pr = smf + PF_OFF + t * SPF + qd * 16;
            __half* ph = smh + PH_OFF + t * SPH + qd * 16;
            float m = -1e30f;
            #pragma unroll
            for (int j = 0; j < 16; j++) m = fmaxf(m, pr[j]);
            m = fmaxf(m, __shfl_xor_sync(0xffffffffu, m, 1));
            m = fmaxf(m, __shfl_xor_sync(0xffffffffu, m, 2));
            float s = 0.f;
            #pragma unroll
            for (int j = 0; j < 16; j++) { const float e = __expf(pr[j] - m); pr[j] = e; s += e; }
            s += __shfl_xor_sync(0xffffffffu, s, 1);
            s += __shfl_xor_sync(0xffffffffu, s, 2);
            const float inv = 1.f / s;
            #pragma unroll
            for (int j = 0; j < 16; j += 2) {
                float2 v = {pr[j] * inv, pr[j + 1] * inv};
                *(half2*)(ph + j) = __float22half2_rn(v);
            }
        }
        __syncthreads();

        // AV: O_h = PH @ V_h  (A = PH stride 72; B = transposed V via LDS.U16)
        for (int t = wid; t < 24; t += 12) {
            const int mi2 = t / 6, ci = t % 6;
            float ao[4] = {0.f, 0.f, 0.f, 0.f};
            const int colv = h * 48 + ci * 8 + gr;
            #pragma unroll
            for (int kk = 0; kk < 4; kk++) {
                const __half* Ap = smh + PH_OFF + (mi2 * 16 + gr) * SPH + kk * 16 + tg * 2;
                const uint32_t a0 = *(const uint32_t*)Ap;
                const uint32_t a1 = *(const uint32_t*)(Ap + 8 * SPH);
                const uint32_t a2 = *(const uint32_t*)(Ap + 8);
                const uint32_t a3 = *(const uint32_t*)(Ap + 8 * SPH + 8);
                const __half* Vb = smh + HV + (kk * 16) * SAH + colv;
                const uint32_t h00 = *(const unsigned short*)(Vb + (2 * tg) * SAH);
                const uint32_t h01 = *(const unsigned short*)(Vb + (2 * tg + 1) * SAH);
                const uint32_t h10 = *(const unsigned short*)(Vb + (8 + 2 * tg) * SAH);
                const uint32_t h11 = *(const unsigned short*)(Vb + (9 + 2 * tg) * SAH);
                mma_f16(ao, a0, a1, a2, a3, h00 | (h01 << 16), h10 | (h11 << 16));
            }
            const int row = mi2 * 16 + gr, col = h * 48 + ci * 8 + 2 * tg;
            float2 v0 = {ao[0], ao[1]}, v1 = {ao[2], ao[3]};
            *(half2*)(smh + HQ + row * SAH + col)       = __float22half2_rn(v0);
            *(half2*)(smh + HQ + (row + 8) * SAH + col) = __float22half2_rn(v1);
        }
        __syncthreads();
    }

    // ---- o-proj + residual RMW into X ----
    {
        float acc[2][4][4];
        #pragma unroll
        for (int s = 0; s < 2; s++)
            #pragma unroll
            for (int n = 0; n < 4; n++)
                #pragma unroll
                for (int r = 0; r < 4; r++) acc[s][n][r] = 0.f;
        gemm_h(smh, HQ, g_wT + WT_O, 192, 0, lane, mi, nj, ringH, acc);
        #pragma unroll
        for (int s = 0; s < 2; s++) {
            const int row = mi * 32 + s * 16 + gr;
            #pragma unroll
            for (int n = 0; n < 4; n++) {
                const int col = nj * 32 + n * 8 + 2 * tg;
                const float bb0 = __ldg(&bo[col]);
                const float bb1 = __ldg(&bo[col + 1]);
                half2* x0 = (half2*)(smh + HX + row * SAH + col);
                half2* x1 = (half2*)(smh + HX + (row + 8) * SAH + col);
                float2 v0 = __half22float2(*x0);
                float2 v1 = __half22float2(*x1);
                v0.x += acc[s][n][0] + bb0; v0.y += acc[s][n][1] + bb1;
                v1.x += acc[s][n][2] + bb0; v1.y += acc[s][n][3] + bb1;
                *x0 = __float22half2_rn(v0);
                *x1 = __float22half2_rn(v1);
            }
        }
    }

    // ---- LN2: X -> H (K slab) ----
    layernorm_h(smh, smf, HX, HK, g2, b2, tid);

    // ---- MLP: 4 hidden slabs of 192; G reuses V slab ----
    float acc2[2][4][4];
    #pragma unroll
    for (int s = 0; s < 2; s++)
        #pragma unroll
        for (int n = 0; n < 4; n++)
            #pragma unroll
            for (int r = 0; r < 4; r++) acc2[s][n][r] = 0.f;

    #pragma unroll 1
    for (int jt = 0; jt < 4; jt++) {
        float acc1[2][4][4];
        #pragma unroll
        for (int s = 0; s < 2; s++)
            #pragma unroll
            for (int n = 0; n < 4; n++)
                #pragma unroll
                for (int r = 0; r < 4; r++) acc1[s][n][r] = 0.f;
        gemm_h(smh, HK, g_wT + WT_M1, 192, jt * 192, lane, mi, nj, ringH, acc1);
        #pragma unroll
        for (int s = 0; s < 2; s++) {
            const int row = mi * 32 + s * 16 + gr;
            #pragma unroll
            for (int n = 0; n < 4; n++) {
                const int col = nj * 32 + n * 8 + 2 * tg;
                const float bb0 = __ldg(&bm1[jt * 192 + col]);
                const float bb1 = __ldg(&bm1[jt * 192 + col + 1]);
                float v0 = acc1[s][n][0] + bb0, v1 = acc1[s][n][1] + bb1;
                float v2 = acc1[s][n][2] + bb0, v3 = acc1[s][n][3] + bb1;
                v0 = 0.5f * v0 * (1.f + erff(v0 * 0.70710678118654752f));
                v1 = 0.5f * v1 * (1.f + erff(v1 * 0.70710678118654752f));
                v2 = 0.5f * v2 * (1.f + erff(v2 * 0.70710678118654752f));
                v3 = 0.5f * v3 * (1.f + erff(v3 * 0.70710678118654752f));
                float2 p0 = {v0, v1}, p1 = {v2, v3};
                *(half2*)(smh + HV + row * SAH + col)       = __float22half2_rn(p0);
                *(half2*)(smh + HV + (row + 8) * SAH + col) = __float22half2_rn(p1);
            }
        }
        __syncthreads();            // G complete before gemm2 reads it
        gemm_h(smh, HV, g_wT + WT_M2 + jt * 192, 768, 0, lane, mi, nj, ringH, acc2);
        __syncthreads();            // G consumed before next jt overwrites
    }

    // ---- residual + staged scatter (3 chunks of 64 cols via P fp32) ----
    {
        for (int ch = 0; ch < 3; ch++) {
            #pragma unroll
            for (int s = 0; s < 2; s++) {
                const int row = mi * 32 + s * 16 + gr;
                #pragma unroll
                for (int n = 0; n < 4; n++) {
                    const int col = nj * 32 + n * 8 + 2 * tg;
                    if ((col >> 6) == ch) {
                        const int cl = col & 63;
                        const float bb0 = __ldg(&bm2[col]);
                        const float bb1 = __ldg(&bm2[col + 1]);
                        const float2 x0 = __half22float2(*(const half2*)(smh + HX + row * SAH + col));
                        const float2 x1 = __half22float2(*(const half2*)(smh + HX + (row + 8) * SAH + col));
                        smf[PF_OFF + cl * SPF + row]           = acc2[s][n][0] + bb0 + x0.x;
                        smf[PF_OFF + (cl + 1) * SPF + row]     = acc2[s][n][1] + bb1 + x0.y;
                        smf[PF_OFF + cl * SPF + row + 8]       = acc2[s][n][2] + bb0 + x1.x;
                        smf[PF_OFF + (cl + 1) * SPF + row + 8] = acc2[s][n][3] + bb1 + x1.y;
                    }
                }
            }
            __syncthreads();
            for (int l = tid; l < 1024; l += 384) {
                const int cl  = l >> 4;
                const int r16 = l & 15;
                const int ty  = r16 >> 1, hf = r16 & 1;
                const int c   = ch * 64 + cl;
                const int sh  = (hb * 8 + ty + 4) & 255;
                const int sw  = (wb * 8 + hf * 4 + 4) & 255;
                const float4 v = *(const float4*)&smf[PF_OFF + cl * SPF + ty * 8 + hf * 4];
                *(float4*)&out[(((size_t)(b * 192 + c)) << 16) + (sh << 8) + sw] = v;
            }
            __syncthreads();
        }
    }
}

extern "C" void kernel_launch(void* const* d_in, const int* in_sizes, int n_in,
                              void* d_out, int out_size)
{
    (void)in_sizes; (void)n_in; (void)out_size;
    const float* x    = (const float*)d_in[0];
    const float* g1   = (const float*)d_in[1];
    const float* b1   = (const float*)d_in[2];
    const float* wqkv = (const float*)d_in[3];
    const float* bqkv = (const float*)d_in[4];
    const float* wo   = (const float*)d_in[5];
    const float* bo   = (const float*)d_in[6];
    const float* g2   = (const float*)d_in[7];
    const float* b2   = (const float*)d_in[8];
    const float* wm1  = (const float*)d_in[9];
    const float* bm1  = (const float*)d_in[10];
    const float* wm2  = (const float*)d_in[11];
    const float* bm2  = (const float*)d_in[12];
    float* out = (float*)d_out;

    cvt_weights<<<(WT_TOTAL + 255) / 256, 256>>>(wqkv, wo, wm1, wm2);
    cudaFuncSetAttribute(swin_block_kernel,
                         cudaFuncAttributeMaxDynamicSharedMemorySize, SMEM_BYTES);
    swin_block_kernel<<<4096, 384, SMEM_BYTES>>>(
        x, g1, b1, bqkv, bo, g2, b2, bm1, bm2, out);
}

// round 13
// speedup vs baseline: 1.3157x; 1.3157x over previous
#include <cuda_runtime.h>
#include <math.h>
#include <stdint.h>

// x: (4,192,256,256) fp32, WS=8, shift=4, NHEADS=4, HD=48, nW=4096, T=64
// 384 threads (12 warps), 1 window/CTA. tf32 mma.sync m16n8k8.
// Weights pre-rewritten into MMA-FRAGMENT ORDER in a __device__ scratch by a
// prologue kernel: per (k8-tile, 32-col slab, lane) the 8 B-frag floats are
// contiguous -> each GEMM k-step is 2 coalesced LDG.128 per warp. No weight
// SMEM, no staging syncs. Warp tile m32 x n32 (2m x 6n).
// Activation buffers t-major stride 196 (=4 mod 32): conflict-free frags.
#define SA 196
#define SP 68
#define OFF_X 0          // LN1 out / residual  64x196 = 12544 f
#define OFF_Q 12544      // Q -> O concat
#define OFF_K 25088      // K -> H (LN2 out)
#define OFF_V 37632      // V -> G (gelu out)
#define OFF_P 50176      // scores 64x68 / LN scratch / out staging (4352 f)
#define SMEM_FLOATS 54528
#define SMEM_BYTES (SMEM_FLOATS * 4)   // 218112 B

// fragment-ordered fp32 weight scratch
// layout: off + ((kt*S + slab)*32 + lane)*8 ; [0..3]=b0(k=tg), [4..7]=b1(k=tg+4)
//   qkv: S=18 slabs (576 cols), 24 kt           -> 110592 f
//   o:   S=6,  24 kt                            ->  36864 f
//   m1:  S=24 (768 cols), 24 kt                 -> 147456 f
//   m2:  4 chunks (jt) each S=6, 24 kt          -> 147456 f
#define WF_QKV 0
#define WF_O   110592
#define WF_M1  147456
#define WF_M2  294912
#define WF_TOTAL 442368
static __device__ __align__(16) float g_wF[WF_TOTAL];

__global__ void cvt_weights(const float* __restrict__ wqkv, const float* __restrict__ wo,
                            const float* __restrict__ wm1,  const float* __restrict__ wm2)
{
    const int i = blockIdx.x * 256 + threadIdx.x;
    if (i >= WF_TOTAL) return;
    const int j    = i & 7;          // frag element
    const int lane = (i >> 3) & 31;
    const int unit = i >> 8;         // (kt*S + slab)
    const int sn = j & 3, isb1 = j >> 2;
    const int gr = lane >> 2, tg = lane & 3;
    float v;
    if (i < WF_O) {                                  // qkv: S=18
        const int slab = unit % 18, kt = unit / 18;
        const int k = kt * 8 + tg + isb1 * 4;
        const int col = slab * 32 + sn * 8 + gr;
        v = wqkv[k * 576 + col];
    } else if (i < WF_M1) {                          // o: S=6
        const int u = unit - WF_O / 256;
        const int slab = u % 6, kt = u / 6;
        const int k = kt * 8 + tg + isb1 * 4;
        const int col = slab * 32 + sn * 8 + gr;
        v = wo[k * 192 + col];
    } else if (i < WF_M2) {                          // m1: S=24
        const int u = unit - WF_M1 / 256;
        const int slab = u % 24, kt = u / 24;
        const int k = kt * 8 + tg + isb1 * 4;
        const int col = slab * 32 + sn * 8 + gr;
        v = wm1[k * 768 + col];
    } else {                                         // m2: 4 chunks, S=6
        const int u = unit - WF_M2 / 256;
        const int chunk = u / (24 * 6);
        const int u2 = u - chunk * 24 * 6;
        const int slab = u2 % 6, kt = u2 / 6;
        const int k = kt * 8 + tg + isb1 * 4;
        const int col = slab * 32 + sn * 8 + gr;
        v = wm2[(chunk * 192 + k) * 192 + col];
    }
    g_wF[i] = v;
}

__device__ __forceinline__ void mma_tf32(float (&d)[4],
                                         uint32_t a0, uint32_t a1, uint32_t a2, uint32_t a3,
                                         uint32_t b0, uint32_t b1)
{
    asm volatile(
        "mma.sync.aligned.m16n8k8.row.col.f32.tf32.tf32.f32 "
        "{%0,%1,%2,%3}, {%4,%5,%6,%7}, {%8,%9}, {%0,%1,%2,%3};"
        : "+f"(d[0]), "+f"(d[1]), "+f"(d[2]), "+f"(d[3])
        : "r"(a0), "r"(a1), "r"(a2), "r"(a3), "r"(b0), "r"(b1));
}

// acc[2][4][4] += A(64x192 smem) @ frag-ordered weights; NO syncs, NO SMEM weights.
// fragBase points at region; S = slabs per kt; slab = this warp's slab index.
__device__ __forceinline__ void gemm_frag(const float* __restrict__ sA,
                                          const float* __restrict__ fragBase,
                                          int S, int slab,
                                          int lane, int mi,
                                          float (&acc)[2][4][4])
{
    const int gr = lane >> 2, tg = lane & 3;
    const float* f0 = fragBase + ((size_t)slab * 32 + lane) * 8;
    const int ktStride = S * 256;
    #pragma unroll 4
    for (int kt = 0; kt < 24; kt++) {
        const float4 q0 = __ldg((const float4*)(f0 + (size_t)kt * ktStride));
        const float4 q1 = __ldg((const float4*)(f0 + (size_t)kt * ktStride + 4));
        const uint32_t b0[4] = {__float_as_uint(q0.x), __float_as_uint(q0.y),
                                __float_as_uint(q0.z), __float_as_uint(q0.w)};
        const uint32_t b1[4] = {__float_as_uint(q1.x), __float_as_uint(q1.y),
                                __float_as_uint(q1.z), __float_as_uint(q1.w)};
        #pragma unroll
        for (int s = 0; s < 2; s++) {
            const float* Ab = sA + (mi * 32 + s * 16 + gr) * SA + kt * 8 + tg;
            const uint32_t a0 = __float_as_uint(Ab[0]);
            const uint32_t a1 = __float_as_uint(Ab[8 * SA]);
            const uint32_t a2 = __float_as_uint(Ab[4]);
            const uint32_t a3 = __float_as_uint(Ab[8 * SA + 4]);
            #pragma unroll
            for (int sn = 0; sn < 4; sn++)
                mma_tf32(acc[s][sn], a0, a1, a2, a3, b0[sn], b1[sn]);
        }
    }
}

// token-parallel LayerNorm on t-major buffers (sync at entry and exit)
__device__ __forceinline__ void layernorm(float* __restrict__ sm,
                                          int src, int dst,
                                          const float* __restrict__ g,
                                          const float* __restrict__ bp,
                                          int tid)
{
    __syncthreads();
    const int t = tid & 63, chk = tid >> 6;       // 6 chunks of 32 channels
    {
        const float* row = &sm[src + t * SA + chk * 32];
        float s = 0.f, s2 = 0.f;
        #pragma unroll
        for (int j4 = 0; j4 < 8; j4++) {
            const float4 v = *(const float4*)&row[j4 * 4];
            s  += v.x + v.y + v.z + v.w;
            s2 += v.x * v.x + v.y * v.y + v.z * v.z + v.w * v.w;
        }
        sm[OFF_P + chk * 64 + t]       = s;
        sm[OFF_P + 384 + chk * 64 + t] = s2;
    }
    __syncthreads();
    if (tid < 64) {
        float s = 0.f, s2 = 0.f;
        #pragma unroll
        for (int ch = 0; ch < 6; ch++) {
            s  += sm[OFF_P + ch * 64 + tid];
            s2 += sm[OFF_P + 384 + ch * 64 + tid];
        }
        const float mean = s * (1.f / 192.f);
        const float var  = s2 * (1.f / 192.f) - mean * mean;
        sm[OFF_P + 768 + tid] = mean;
        sm[OFF_P + 832 + tid] = rsqrtf(var + 1e-5f);
    }
    __syncthreads();
    {
        const float mean = sm[OFF_P + 768 + t];
        const float rstd = sm[OFF_P + 832 + t];
        const float* row = &sm[src + t * SA + chk * 32];
        float* drow = &sm[dst + t * SA + chk * 32];
        #pragma unroll
        for (int j4 = 0; j4 < 8; j4++) {
            float4 v = *(const float4*)&row[j4 * 4];
            const float4 gg = *(const float4*)&g[chk * 32 + j4 * 4];
            const float4 bb = *(const float4*)&bp[chk * 32 + j4 * 4];
            v.x = (v.x - mean) * rstd * gg.x + bb.x;
            v.y = (v.y - mean) * rstd * gg.y + bb.y;
            v.z = (v.z - mean) * rstd * gg.z + bb.z;
            v.w = (v.w - mean) * rstd * gg.w + bb.w;
            *(float4*)&drow[j4 * 4] = v;
        }
    }
    __syncthreads();
}

__global__ __launch_bounds__(384, 1)
void swin_block_kernel(const float* __restrict__ x,
                       const float* __restrict__ g1,  const float* __restrict__ b1,
                       const float* __restrict__ bqkv,
                       const float* __restrict__ bo,
                       const float* __restrict__ g2,  const float* __restrict__ b2,
                       const float* __restrict__ bm1, const float* __restrict__ bm2,
                       float* __restrict__ out)
{
    extern __shared__ float sm[];
    const int tid  = threadIdx.x;
    const int wid  = tid >> 5;
    const int lane = tid & 31;
    const int gr   = lane >> 2, tg = lane & 3;
    const int mi   = wid & 1;               // 2 m-tiles of 32 rows
    const int nj   = wid >> 1;              // 6 n-tiles of 32 cols
    const int wi   = blockIdx.x;
    const int b    = wi >> 10;
    const int hb   = (wi >> 5) & 31;
    const int wb   = wi & 31;

    // ---- gather window into X (t-major), shift folded, coalesced gmem float4 ----
    for (int l = tid; l < 3072; l += 384) {
        const int c    = l >> 4;
        const int r16  = l & 15;
        const int ty   = r16 >> 1, half = r16 & 1;
        const int sh   = (hb * 8 + ty + 4) & 255;
        const int sw   = (wb * 8 + half * 4 + 4) & 255;
        const float4 v = *(const float4*)&x[(((size_t)(b * 192 + c)) << 16) + (sh << 8) + sw];
        const int t0 = ty * 8 + half * 4;
        sm[OFF_X + (t0 + 0) * SA + c] = v.x;
        sm[OFF_X + (t0 + 1) * SA + c] = v.y;
        sm[OFF_X + (t0 + 2) * SA + c] = v.z;
        sm[OFF_X + (t0 + 3) * SA + c] = v.w;
    }

    // ---- LN1 in place (residual base = LN1 output) ----
    layernorm(sm, OFF_X, OFF_X, g1, b1, tid);

    // ---- q / k / v GEMMs (fragment-direct, zero syncs) ----
    #pragma unroll 1
    for (int p = 0; p < 3; p++) {
        float acc[2][4][4];
        #pragma unroll
        for (int s = 0; s < 2; s++)
            #pragma unroll
            for (int n = 0; n < 4; n++)
                #pragma unroll
                for (int r = 0; r < 4; r++) acc[s][n][r] = 0.f;
        gemm_frag(&sm[OFF_X], g_wF + WF_QKV, 18, p * 6 + nj, lane, mi, acc);
        float* dst = &sm[(p == 0) ? OFF_Q : (p == 1) ? OFF_K : OFF_V];
        #pragma unroll
        for (int s = 0; s < 2; s++) {
            const int row = mi * 32 + s * 16 + gr;
            #pragma unroll
            for (int n = 0; n < 4; n++) {
                const int col = nj * 32 + n * 8 + 2 * tg;
                const float bb0 = __ldg(&bqkv[p * 192 + col]);
                const float bb1 = __ldg(&bqkv[p * 192 + col + 1]);
                dst[row * SA + col]           = acc[s][n][0] + bb0;
                dst[row * SA + col + 1]       = acc[s][n][1] + bb1;
                dst[(row + 8) * SA + col]     = acc[s][n][2] + bb0;
                dst[(row + 8) * SA + col + 1] = acc[s][n][3] + bb1;
            }
        }
    }
    __syncthreads();

    // ---- attention per head (tf32 mma); O written into Q slab in place ----
    const float scale = 0.14433756729740643f;     // 1/sqrt(48)
    for (int h = 0; h < 4; h++) {
        // scores: S = Q_h @ K_h^T  (B-frag = transposed read of t-major K)
        for (int t = wid; t < 32; t += 12) {
            const int mi2 = t >> 3, ni = t & 7;
            float sc[4] = {0.f, 0.f, 0.f, 0.f};
            const float* Ab = &sm[OFF_Q + (mi2 * 16 + gr) * SA + h * 48 + tg];
            const float* Bb = &sm[OFF_K + (ni * 8 + gr) * SA + h * 48 + tg];
            #pragma unroll
            for (int k8 = 0; k8 < 6; k8++) {
                const uint32_t a0 = __float_as_uint(Ab[k8 * 8]);
                const uint32_t a1 = __float_as_uint(Ab[8 * SA + k8 * 8]);
                const uint32_t a2 = __float_as_uint(Ab[k8 * 8 + 4]);
                const uint32_t a3 = __float_as_uint(Ab[8 * SA + k8 * 8 + 4]);
                const uint32_t b0 = __float_as_uint(Bb[k8 * 8]);
                const uint32_t b1 = __float_as_uint(Bb[k8 * 8 + 4]);
                mma_tf32(sc, a0, a1, a2, a3, b0, b1);
            }
            const int row = mi2 * 16 + gr, col = ni * 8 + 2 * tg;
            sm[OFF_P + row * SP + col]           = sc[0] * scale;
            sm[OFF_P + row * SP + col + 1]       = sc[1] * scale;
            sm[OFF_P + (row + 8) * SP + col]     = sc[2] * scale;
            sm[OFF_P + (row + 8) * SP + col + 1] = sc[3] * scale;
        }
        __syncthreads();

        if (tid < 256) {          // softmax over 64 keys (4 threads/row), fp32 exact
            const int t = tid >> 2, qd = tid & 3;
            float* pr = &sm[OFF_P + t * SP + qd * 16];
            float m = -1e30f;
            #pragma unroll
            for (int j = 0; j < 16; j++) m = fmaxf(m, pr[j]);
            m = fmaxf(m, __shfl_xor_sync(0xffffffffu, m, 1));
            m = fmaxf(m, __shfl_xor_sync(0xffffffffu, m, 2));
            float s = 0.f;
            #pragma unroll
            for (int j = 0; j < 16; j++) { const float e = __expf(pr[j] - m); pr[j] = e; s += e; }
            s += __shfl_xor_sync(0xffffffffu, s, 1);
            s += __shfl_xor_sync(0xffffffffu, s, 2);
            const float inv = 1.f / s;
            #pragma unroll
            for (int j = 0; j < 16; j++) pr[j] *= inv;
        }
        __syncthreads();

        // AV: O_h = P @ V_h  (A = P stride 68, B-frag = transposed V)
        for (int t = wid; t < 24; t += 12) {
            const int mi2 = t / 6, ci = t % 6;
            float ao[4] = {0.f, 0.f, 0.f, 0.f};
            const float* Ab = &sm[OFF_P + (mi2 * 16 + gr) * SP + tg];
            const float* Bb = &sm[OFF_V + tg * SA + h * 48 + ci * 8 + gr];
            #pragma unroll
            for (int k8 = 0; k8 < 8; k8++) {
                const uint32_t a0 = __float_as_uint(Ab[k8 * 8]);
                const uint32_t a1 = __float_as_uint(Ab[8 * SP + k8 * 8]);
                const uint32_t a2 = __float_as_uint(Ab[k8 * 8 + 4]);
                const uint32_t a3 = __float_as_uint(Ab[8 * SP + k8 * 8 + 4]);
                const uint32_t b0 = __float_as_uint(Bb[k8 * 8 * SA]);
                const uint32_t b1 = __float_as_uint(Bb[(k8 * 8 + 4) * SA]);
                mma_tf32(ao, a0, a1, a2, a3, b0, b1);
            }
            const int row = mi2 * 16 + gr, col = h * 48 + ci * 8 + 2 * tg;
            sm[OFF_Q + row * SA + col]           = ao[0];
            sm[OFF_Q + row * SA + col + 1]       = ao[1];
            sm[OFF_Q + (row + 8) * SA + col]     = ao[2];
            sm[OFF_Q + (row + 8) * SA + col + 1] = ao[3];
        }
        __syncthreads();
    }

    // ---- o-proj + residual RMW into X ----
    {
        float acc[2][4][4];
        #pragma unroll
        for (int s = 0; s < 2; s++)
            #pragma unroll
            for (int n = 0; n < 4; n++)
                #pragma unroll
                for (int r = 0; r < 4; r++) acc[s][n][r] = 0.f;
        gemm_frag(&sm[OFF_Q], g_wF + WF_O, 6, nj, lane, mi, acc);
        #pragma unroll
        for (int s = 0; s < 2; s++) {
            const int row = mi * 32 + s * 16 + gr;
            #pragma unroll
            for (int n = 0; n < 4; n++) {
                const int col = nj * 32 + n * 8 + 2 * tg;
                const float bb0 = __ldg(&bo[col]);
                const float bb1 = __ldg(&bo[col + 1]);
                sm[OFF_X + row * SA + col]           += acc[s][n][0] + bb0;
                sm[OFF_X + row * SA + col + 1]       += acc[s][n][1] + bb1;
                sm[OFF_X + (row + 8) * SA + col]     += acc[s][n][2] + bb0;
                sm[OFF_X + (row + 8) * SA + col + 1] += acc[s][n][3] + bb1;
            }
        }
    }

    // ---- LN2: X -> H (K slab) ----
    layernorm(sm, OFF_X, OFF_K, g2, b2, tid);

    // ---- MLP: 4 hidden slabs of 192; G reuses V slab ----
    float acc2[2][4][4];
    #pragma unroll
    for (int s = 0; s < 2; s++)
        #pragma unroll
        for (int n = 0; n < 4; n++)
            #pragma unroll
            for (int r = 0; r < 4; r++) acc2[s][n][r] = 0.f;

    #pragma unroll 1
    for (int jt = 0; jt < 4; jt++) {
        float acc1[2][4][4];
        #pragma unroll
        for (int s = 0; s < 2; s++)
            #pragma unroll
            for (int n = 0; n < 4; n++)
                #pragma unroll
                for (int r = 0; r < 4; r++) acc1[s][n][r] = 0.f;
        gemm_frag(&sm[OFF_K], g_wF + WF_M1, 24, jt * 6 + nj, lane, mi, acc1);
        #pragma unroll
        for (int s = 0; s < 2; s++) {
            const int row = mi * 32 + s * 16 + gr;
            #pragma unroll
            for (int n = 0; n < 4; n++) {
                const int col = nj * 32 + n * 8 + 2 * tg;
                const float bb0 = __ldg(&bm1[jt * 192 + col]);
                const float bb1 = __ldg(&bm1[jt * 192 + col + 1]);
                float v0 = acc1[s][n][0] + bb0, v1 = acc1[s][n][1] + bb1;
                float v2 = acc1[s][n][2] + bb0, v3 = acc1[s][n][3] + bb1;
                v0 = 0.5f * v0 * (1.f + erff(v0 * 0.70710678118654752f));
                v1 = 0.5f * v1 * (1.f + erff(v1 * 0.70710678118654752f));
                v2 = 0.5f * v2 * (1.f + erff(v2 * 0.70710678118654752f));
                v3 = 0.5f * v3 * (1.f + erff(v3 * 0.70710678118654752f));
                sm[OFF_V + row * SA + col]           = v0;
                sm[OFF_V + row * SA + col + 1]       = v1;
                sm[OFF_V + (row + 8) * SA + col]     = v2;
                sm[OFF_V + (row + 8) * SA + col + 1] = v3;
            }
        }
        __syncthreads();            // G complete before gemm2 reads it
        gemm_frag(&sm[OFF_V], g_wF + WF_M2 + jt * 36864, 6, nj, lane, mi, acc2);
        __syncthreads();            // G consumed before next jt overwrites
    }

    // ---- residual + staged scatter (3 chunks of 64 cols via P) ----
    {
        for (int ch = 0; ch < 3; ch++) {
            #pragma unroll
            for (int s = 0; s < 2; s++) {
                const int row = mi * 32 + s * 16 + gr;
                #pragma unroll
                for (int n = 0; n < 4; n++) {
                    const int col = nj * 32 + n * 8 + 2 * tg;
                    if ((col >> 6) == ch) {
                        const int cl = col & 63;
                        const float bb0 = __ldg(&bm2[col]);
                        const float bb1 = __ldg(&bm2[col + 1]);
                        sm[OFF_P + cl * SP + row]           = acc2[s][n][0] + bb0 + sm[OFF_X + row * SA + col];
                        sm[OFF_P + (cl + 1) * SP + row]     = acc2[s][n][1] + bb1 + sm[OFF_X + row * SA + col + 1];
                        sm[OFF_P + cl * SP + row + 8]       = acc2[s][n][2] + bb0 + sm[OFF_X + (row + 8) * SA + col];
                        sm[OFF_P + (cl + 1) * SP + row + 8] = acc2[s][n][3] + bb1 + sm[OFF_X + (row + 8) * SA + col + 1];
                    }
                }
            }
            __syncthreads();
            for (int l = tid; l < 1024; l += 384) {
                const int cl  = l >> 4;
                const int r16 = l & 15;
                const int ty  = r16 >> 1, half = r16 & 1;
                const int c   = ch * 64 + cl;
                const int sh  = (hb * 8 + ty + 4) & 255;
                const int sw  = (wb * 8 + half * 4 + 4) & 255;
                const float4 v = *(const float4*)&sm[OFF_P + cl * SP + ty * 8 + half * 4];
                *(float4*)&out[(((size_t)(b * 192 + c)) << 16) + (sh << 8) + sw] = v;
            }
            __syncthreads();
        }
    }
}

extern "C" void kernel_launch(void* const* d_in, const int* in_sizes, int n_in,
                              void* d_out, int out_size)
{
    (void)in_sizes; (void)n_in; (void)out_size;
    const float* x    = (const float*)d_in[0];
    const float* g1   = (const float*)d_in[1];
    const float* b1   = (const float*)d_in[2];
    const float* wqkv = (const float*)d_in[3];
    const float* bqkv = (const float*)d_in[4];
    const float* wo   = (const float*)d_in[5];
    const float* bo   = (const float*)d_in[6];
    const float* g2   = (const float*)d_in[7];
    const float* b2   = (const float*)d_in[8];
    const float* wm1  = (const float*)d_in[9];
    const float* bm1  = (const float*)d_in[10];
    const float* wm2  = (const float*)d_in[11];
    const float* bm2  = (const float*)d_in[12];
    float* out = (float*)d_out;

    cvt_weights<<<(WF_TOTAL + 255) / 256, 256>>>(wqkv, wo, wm1, wm2);
    cudaFuncSetAttribute(swin_block_kernel,
                         cudaFuncAttributeMaxDynamicSharedMemorySize, SMEM_BYTES);
    swin_block_kernel<<<4096, 384, SMEM_BYTES>>>(
        x, g1, b1, bqkv, bo, g2, b2, bm1, bm2, out);
}

// round 14
// speedup vs baseline: 1.4210x; 1.0800x over previous
#include <cuda_runtime.h>
#include <math.h>
#include <stdint.h>

// x: (4,192,256,256) fp32, WS=8, shift=4, NHEADS=4, HD=48, nW=4096, T=64
// 384 threads (12 warps), 1 window/CTA. tf32 mma.sync m16n8k8.
// Weights in MMA-FRAGMENT ORDER in __device__ scratch (prologue kernel):
// each GEMM k-step = 2 coalesced LDG.128/warp, pointer-bumped. No weight SMEM.
// Attention: fully fused per-(head,16rows) warp tasks — scores m16n64,
// IN-REGISTER softmax (quad shfl), shfl-transposed A-frags, AV m16n48,
// O in place. ZERO barriers inside attention. Warp GEMM tile m32 x n32.
// Activation buffers t-major stride 196 (=4 mod 32): conflict-free frags.
#define SA 196
#define SP 68
#define OFF_X 0          // LN1 out / residual  64x196 = 12544 f
#define OFF_Q 12544      // Q -> O concat
#define OFF_K 25088      // K -> H (LN2 out)
#define OFF_V 37632      // V -> G (gelu out)
#define OFF_P 50176      // LN scratch / out staging (4352 f)
#define SMEM_FLOATS 54528
#define SMEM_BYTES (SMEM_FLOATS * 4)   // 218112 B

// fragment-ordered fp32 weight scratch
// layout: off + ((kt*S + slab)*32 + lane)*8 ; [0..3]=b0(k=tg), [4..7]=b1(k=tg+4)
#define WF_QKV 0
#define WF_O   110592
#define WF_M1  147456
#define WF_M2  294912
#define WF_TOTAL 442368
static __device__ __align__(16) float g_wF[WF_TOTAL];

__global__ void cvt_weights(const float* __restrict__ wqkv, const float* __restrict__ wo,
                            const float* __restrict__ wm1,  const float* __restrict__ wm2)
{
    const int i = blockIdx.x * 256 + threadIdx.x;
    if (i >= WF_TOTAL) return;
    const int j    = i & 7;
    const int lane = (i >> 3) & 31;
    const int unit = i >> 8;
    const int sn = j & 3, isb1 = j >> 2;
    const int gr = lane >> 2, tg = lane & 3;
    float v;
    if (i < WF_O) {                                  // qkv: S=18
        const int slab = unit % 18, kt = unit / 18;
        const int k = kt * 8 + tg + isb1 * 4;
        const int col = slab * 32 + sn * 8 + gr;
        v = wqkv[k * 576 + col];
    } else if (i < WF_M1) {                          // o: S=6
        const int u = unit - WF_O / 256;
        const int slab = u % 6, kt = u / 6;
        const int k = kt * 8 + tg + isb1 * 4;
        const int col = slab * 32 + sn * 8 + gr;
        v = wo[k * 192 + col];
    } else if (i < WF_M2) {                          // m1: S=24
        const int u = unit - WF_M1 / 256;
        const int slab = u % 24, kt = u / 24;
        const int k = kt * 8 + tg + isb1 * 4;
        const int col = slab * 32 + sn * 8 + gr;
        v = wm1[k * 768 + col];
    } else {                                         // m2: 4 chunks, S=6
        const int u = unit - WF_M2 / 256;
        const int chunk = u / (24 * 6);
        const int u2 = u - chunk * 24 * 6;
        const int slab = u2 % 6, kt = u2 / 6;
        const int k = kt * 8 + tg + isb1 * 4;
        const int col = slab * 32 + sn * 8 + gr;
        v = wm2[(chunk * 192 + k) * 192 + col];
    }
    g_wF[i] = v;
}

__device__ __forceinline__ void mma_tf32(float (&d)[4],
                                         uint32_t a0, uint32_t a1, uint32_t a2, uint32_t a3,
                                         uint32_t b0, uint32_t b1)
{
    asm volatile(
        "mma.sync.aligned.m16n8k8.row.col.f32.tf32.tf32.f32 "
        "{%0,%1,%2,%3}, {%4,%5,%6,%7}, {%8,%9}, {%0,%1,%2,%3};"
        : "+f"(d[0]), "+f"(d[1]), "+f"(d[2]), "+f"(d[3])
        : "r"(a0), "r"(a1), "r"(a2), "r"(a3), "r"(b0), "r"(b1));
}

// acc[2][4][4] += A(64x192 smem) @ frag-ordered weights; no syncs, no weight SMEM
__device__ __forceinline__ void gemm_frag(const float* __restrict__ sA,
                                          const float* __restrict__ fragBase,
                                          int S, int slab,
                                          int lane, int mi,
                                          float (&acc)[2][4][4])
{
    const int gr = lane >> 2, tg = lane & 3;
    const float4* fp = (const float4*)(fragBase + ((size_t)slab * 32 + lane) * 8);
    const int step4 = S * 64;                     // float4s per kt
    const float* A0 = sA + (mi * 32 + gr) * SA + tg;
    #pragma unroll 4
    for (int kt = 0; kt < 24; kt++) {
        const float4 q0 = __ldg(fp);
        const float4 q1 = __ldg(fp + 1);
        fp += step4;
        const uint32_t b0[4] = {__float_as_uint(q0.x), __float_as_uint(q0.y),
                                __float_as_uint(q0.z), __float_as_uint(q0.w)};
        const uint32_t b1[4] = {__float_as_uint(q1.x), __float_as_uint(q1.y),
                                __float_as_uint(q1.z), __float_as_uint(q1.w)};
        #pragma unroll
        for (int s = 0; s < 2; s++) {
            const float* Ab = A0 + s * 16 * SA + kt * 8;
            const uint32_t a0 = __float_as_uint(Ab[0]);
            const uint32_t a1 = __float_as_uint(Ab[8 * SA]);
            const uint32_t a2 = __float_as_uint(Ab[4]);
            const uint32_t a3 = __float_as_uint(Ab[8 * SA + 4]);
            #pragma unroll
            for (int sn = 0; sn < 4; sn++)
                mma_tf32(acc[s][sn], a0, a1, a2, a3, b0[sn], b1[sn]);
        }
    }
}

// token-parallel LayerNorm on t-major buffers (sync at entry and exit)
__device__ __forceinline__ void layernorm(float* __restrict__ sm,
                                          int src, int dst,
                                          const float* __restrict__ g,
                                          const float* __restrict__ bp,
                                          int tid)
{
    __syncthreads();
    const int t = tid & 63, chk = tid >> 6;       // 6 chunks of 32 channels
    {
        const float* row = &sm[src + t * SA + chk * 32];
        float s = 0.f, s2 = 0.f;
        #pragma unroll
        for (int j4 = 0; j4 < 8; j4++) {
            const float4 v = *(const float4*)&row[j4 * 4];
            s  += v.x + v.y + v.z + v.w;
            s2 += v.x * v.x + v.y * v.y + v.z * v.z + v.w * v.w;
        }
        sm[OFF_P + chk * 64 + t]       = s;
        sm[OFF_P + 384 + chk * 64 + t] = s2;
    }
    __syncthreads();
    if (tid < 64) {
        float s = 0.f, s2 = 0.f;
        #pragma unroll
        for (int ch = 0; ch < 6; ch++) {
            s  += sm[OFF_P + ch * 64 + tid];
            s2 += sm[OFF_P + 384 + ch * 64 + tid];
        }
        const float mean = s * (1.f / 192.f);
        const float var  = s2 * (1.f / 192.f) - mean * mean;
        sm[OFF_P + 768 + tid] = mean;
        sm[OFF_P + 832 + tid] = rsqrtf(var + 1e-5f);
    }
    __syncthreads();
    {
        const float mean = sm[OFF_P + 768 + t];
        const float rstd = sm[OFF_P + 832 + t];
        const float* row = &sm[src + t * SA + chk * 32];
        float* drow = &sm[dst + t * SA + chk * 32];
        #pragma unroll
        for (int j4 = 0; j4 < 8; j4++) {
            float4 v = *(const float4*)&row[j4 * 4];
            const float4 gg = *(const float4*)&g[chk * 32 + j4 * 4];
            const float4 bb = *(const float4*)&bp[chk * 32 + j4 * 4];
            v.x = (v.x - mean) * rstd * gg.x + bb.x;
            v.y = (v.y - mean) * rstd * gg.y + bb.y;
            v.z = (v.z - mean) * rstd * gg.z + bb.z;
            v.w = (v.w - mean) * rstd * gg.w + bb.w;
            *(float4*)&drow[j4 * 4] = v;
        }
    }
    __syncthreads();
}

__global__ __launch_bounds__(384, 1)
void swin_block_kernel(const float* __restrict__ x,
                       const float* __restrict__ g1,  const float* __restrict__ b1,
                       const float* __restrict__ bqkv,
                       const float* __restrict__ bo,
                       const float* __restrict__ g2,  const float* __restrict__ b2,
                       const float* __restrict__ bm1, const float* __restrict__ bm2,
                       float* __restrict__ out)
{
    extern __shared__ float sm[];
    const int tid  = threadIdx.x;
    const int wid  = tid >> 5;
    const int lane = tid & 31;
    const int gr   = lane >> 2, tg = lane & 3;
    const int mi   = wid & 1;               // 2 m-tiles of 32 rows
    const int nj   = wid >> 1;              // 6 n-tiles of 32 cols
    const int wi   = blockIdx.x;
    const int b    = wi >> 10;
    const int hb   = (wi >> 5) & 31;
    const int wb   = wi & 31;

    // ---- gather window into X (t-major), shift folded, coalesced gmem float4 ----
    for (int l = tid; l < 3072; l += 384) {
        const int c    = l >> 4;
        const int r16  = l & 15;
        const int ty   = r16 >> 1, half = r16 & 1;
        const int sh   = (hb * 8 + ty + 4) & 255;
        const int sw   = (wb * 8 + half * 4 + 4) & 255;
        const float4 v = *(const float4*)&x[(((size_t)(b * 192 + c)) << 16) + (sh << 8) + sw];
        const int t0 = ty * 8 + half * 4;
        sm[OFF_X + (t0 + 0) * SA + c] = v.x;
        sm[OFF_X + (t0 + 1) * SA + c] = v.y;
        sm[OFF_X + (t0 + 2) * SA + c] = v.z;
        sm[OFF_X + (t0 + 3) * SA + c] = v.w;
    }

    // ---- LN1 in place (residual base = LN1 output) ----
    layernorm(sm, OFF_X, OFF_X, g1, b1, tid);

    // ---- q / k / v GEMMs (fragment-direct, zero syncs) ----
    #pragma unroll 1
    for (int p = 0; p < 3; p++) {
        float acc[2][4][4];
        #pragma unroll
        for (int s = 0; s < 2; s++)
            #pragma unroll
            for (int n = 0; n < 4; n++)
                #pragma unroll
                for (int r = 0; r < 4; r++) acc[s][n][r] = 0.f;
        gemm_frag(&sm[OFF_X], g_wF + WF_QKV, 18, p * 6 + nj, lane, mi, acc);
        float* dst = &sm[(p == 0) ? OFF_Q : (p == 1) ? OFF_K : OFF_V];
        #pragma unroll
        for (int s = 0; s < 2; s++) {
            const int row = mi * 32 + s * 16 + gr;
            #pragma unroll
            for (int n = 0; n < 4; n++) {
                const int col = nj * 32 + n * 8 + 2 * tg;
                const float bb0 = __ldg(&bqkv[p * 192 + col]);
                const float bb1 = __ldg(&bqkv[p * 192 + col + 1]);
                dst[row * SA + col]           = acc[s][n][0] + bb0;
                dst[row * SA + col + 1]       = acc[s][n][1] + bb1;
                dst[(row + 8) * SA + col]     = acc[s][n][2] + bb0;
                dst[(row + 8) * SA + col + 1] = acc[s][n][3] + bb1;
            }
        }
    }
    __syncthreads();

    // ---- attention: 16 warp-tasks (head h, 16-row tile mi2); ZERO barriers ----
    // scores m16n64 -> in-register softmax -> shfl-transposed A-frags -> AV m16n48
    const float scale = 0.14433756729740643f;     // 1/sqrt(48)
    for (int task = wid; task < 16; task += 12) {
        const int h = task >> 2, mi2 = task & 3;
        // scores: sc[ni][{r,r+1 cols 2tg,2tg+1} x {row gr, row gr+8}]
        float sc[8][4];
        #pragma unroll
        for (int ni = 0; ni < 8; ni++)
            #pragma unroll
            for (int r = 0; r < 4; r++) sc[ni][r] = 0.f;
        {
            const float* Ab = &sm[OFF_Q + (mi2 * 16 + gr) * SA + h * 48 + tg];
            const float* Bb = &sm[OFF_K + gr * SA + h * 48 + tg];
            #pragma unroll
            for (int k8 = 0; k8 < 6; k8++) {
                const uint32_t a0 = __float_as_uint(Ab[k8 * 8]);
                const uint32_t a1 = __float_as_uint(Ab[8 * SA + k8 * 8]);
                const uint32_t a2 = __float_as_uint(Ab[k8 * 8 + 4]);
                const uint32_t a3 = __float_as_uint(Ab[8 * SA + k8 * 8 + 4]);
                #pragma unroll
                for (int ni = 0; ni < 8; ni++) {
                    const uint32_t b0 = __float_as_uint(Bb[ni * 8 * SA + k8 * 8]);
                    const uint32_t b1 = __float_as_uint(Bb[ni * 8 * SA + k8 * 8 + 4]);
                    mma_tf32(sc[ni], a0, a1, a2, a3, b0, b1);
                }
            }
        }
        // in-register softmax over 64 cols; rows gr (elems 0,1) and gr+8 (2,3)
        {
            float m0 = -1e30f, m1 = -1e30f;
            #pragma unroll
            for (int ni = 0; ni < 8; ni++) {
                #pragma unroll
                for (int r = 0; r < 4; r++) sc[ni][r] *= scale;
                m0 = fmaxf(m0, fmaxf(sc[ni][0], sc[ni][1]));
                m1 = fmaxf(m1, fmaxf(sc[ni][2], sc[ni][3]));
            }
            m0 = fmaxf(m0, __shfl_xor_sync(0xffffffffu, m0, 1));
            m0 = fmaxf(m0, __shfl_xor_sync(0xffffffffu, m0, 2));
            m1 = fmaxf(m1, __shfl_xor_sync(0xffffffffu, m1, 1));
            m1 = fmaxf(m1, __shfl_xor_sync(0xffffffffu, m1, 2));
            float s0 = 0.f, s1 = 0.f;
            #pragma unroll
            for (int ni = 0; ni < 8; ni++) {
                sc[ni][0] = __expf(sc[ni][0] - m0);
                sc[ni][1] = __expf(sc[ni][1] - m0);
                sc[ni][2] = __expf(sc[ni][2] - m1);
                sc[ni][3] = __expf(sc[ni][3] - m1);
                s0 += sc[ni][0] + sc[ni][1];
                s1 += sc[ni][2] + sc[ni][3];
            }
            s0 += __shfl_xor_sync(0xffffffffu, s0, 1);
            s0 += __shfl_xor_sync(0xffffffffu, s0, 2);
            s1 += __shfl_xor_sync(0xffffffffu, s1, 1);
            s1 += __shfl_xor_sync(0xffffffffu, s1, 2);
            const float i0 = 1.f / s0, i1 = 1.f / s1;
            #pragma unroll
            for (int ni = 0; ni < 8; ni++) {
                sc[ni][0] *= i0; sc[ni][1] *= i0;
                sc[ni][2] *= i1; sc[ni][3] *= i1;
            }
        }
        // AV: A-frags from sc via shfl transpose (fixed source lanes)
        {
            float ao[6][4];
            #pragma unroll
            for (int ci = 0; ci < 6; ci++)
                #pragma unroll
                for (int r = 0; r < 4; r++) ao[ci][r] = 0.f;
            const int sl0 = gr * 4 + (tg >> 1);
            const int sl1 = sl0 + 2;
            const int odd = tg & 1;
            const float* Vb = &sm[OFF_V + tg * SA + h * 48 + gr];
            #pragma unroll
            for (int kk = 0; kk < 8; kk++) {
                const float t00 = __shfl_sync(0xffffffffu, sc[kk][0], sl0);
                const float t01 = __shfl_sync(0xffffffffu, sc[kk][1], sl0);
                const float t20 = __shfl_sync(0xffffffffu, sc[kk][0], sl1);
                const float t21 = __shfl_sync(0xffffffffu, sc[kk][1], sl1);
                const float t10 = __shfl_sync(0xffffffffu, sc[kk][2], sl0);
                const float t11 = __shfl_sync(0xffffffffu, sc[kk][3], sl0);
                const float t30 = __shfl_sync(0xffffffffu, sc[kk][2], sl1);
                const float t31 = __shfl_sync(0xffffffffu, sc[kk][3], sl1);
                const uint32_t a0 = __float_as_uint(odd ? t01 : t00);
                const uint32_t a2 = __float_as_uint(odd ? t21 : t20);
                const uint32_t a1 = __float_as_uint(odd ? t11 : t10);
                const uint32_t a3 = __float_as_uint(odd ? t31 : t30);
                #pragma unroll
                for (int ci = 0; ci < 6; ci++) {
                    const uint32_t b0 = __float_as_uint(Vb[(kk * 8) * SA + ci * 8]);
                    const uint32_t b1 = __float_as_uint(Vb[(kk * 8 + 4) * SA + ci * 8]);
                    mma_tf32(ao[ci], a0, a1, a2, a3, b0, b1);
                }
            }
            const int row = mi2 * 16 + gr;
            #pragma unroll
            for (int ci = 0; ci < 6; ci++) {
                const int col = h * 48 + ci * 8 + 2 * tg;
                sm[OFF_Q + row * SA + col]           = ao[ci][0];
                sm[OFF_Q + row * SA + col + 1]       = ao[ci][1];
                sm[OFF_Q + (row + 8) * SA + col]     = ao[ci][2];
                sm[OFF_Q + (row + 8) * SA + col + 1] = ao[ci][3];
            }
        }
    }
    __syncthreads();

    // ---- o-proj + residual RMW into X ----
    {
        float acc[2][4][4];
        #pragma unroll
        for (int s = 0; s < 2; s++)
            #pragma unroll
            for (int n = 0; n < 4; n++)
                #pragma unroll
                for (int r = 0; r < 4; r++) acc[s][n][r] = 0.f;
        gemm_frag(&sm[OFF_Q], g_wF + WF_O, 6, nj, lane, mi, acc);
        #pragma unroll
        for (int s = 0; s < 2; s++) {
            const int row = mi * 32 + s * 16 + gr;
            #pragma unroll
            for (int n = 0; n < 4; n++) {
                const int col = nj * 32 + n * 8 + 2 * tg;
                const float bb0 = __ldg(&bo[col]);
                const float bb1 = __ldg(&bo[col + 1]);
                sm[OFF_X + row * SA + col]           += acc[s][n][0] + bb0;
                sm[OFF_X + row * SA + col + 1]       += acc[s][n][1] + bb1;
                sm[OFF_X + (row + 8) * SA + col]     += acc[s][n][2] + bb0;
                sm[OFF_X + (row + 8) * SA + col + 1] += acc[s][n][3] + bb1;
            }
        }
    }

    // ---- LN2: X -> H (K slab) ----
    layernorm(sm, OFF_X, OFF_K, g2, b2, tid);

    // ---- MLP: 4 hidden slabs of 192; G reuses V slab ----
    float acc2[2][4][4];
    #pragma unroll
    for (int s = 0; s < 2; s++)
        #pragma unroll
        for (int n = 0; n < 4; n++)
            #pragma unroll
            for (int r = 0; r < 4; r++) acc2[s][n][r] = 0.f;

    #pragma unroll 1
    for (int jt = 0; jt < 4; jt++) {
        float acc1[2][4][4];
        #pragma unroll
        for (int s = 0; s < 2; s++)
            #pragma unroll
            for (int n = 0; n < 4; n++)
                #pragma unroll
                for (int r = 0; r < 4; r++) acc1[s][n][r] = 0.f;
        gemm_frag(&sm[OFF_K], g_wF + WF_M1, 24, jt * 6 + nj, lane, mi, acc1);
        #pragma unroll
        for (int s = 0; s < 2; s++) {
            const int row = mi * 32 + s * 16 + gr;
            #pragma unroll
            for (int n = 0; n < 4; n++) {
                const int col = nj * 32 + n * 8 + 2 * tg;
                const float bb0 = __ldg(&bm1[jt * 192 + col]);
                const float bb1 = __ldg(&bm1[jt * 192 + col + 1]);
                float v0 = acc1[s][n][0] + bb0, v1 = acc1[s][n][1] + bb1;
                float v2 = acc1[s][n][2] + bb0, v3 = acc1[s][n][3] + bb1;
                v0 = 0.5f * v0 * (1.f + erff(v0 * 0.70710678118654752f));
                v1 = 0.5f * v1 * (1.f + erff(v1 * 0.70710678118654752f));
                v2 = 0.5f * v2 * (1.f + erff(v2 * 0.70710678118654752f));
                v3 = 0.5f * v3 * (1.f + erff(v3 * 0.70710678118654752f));
                sm[OFF_V + row * SA + col]           = v0;
                sm[OFF_V + row * SA + col + 1]       = v1;
                sm[OFF_V + (row + 8) * SA + col]     = v2;
                sm[OFF_V + (row + 8) * SA + col + 1] = v3;
            }
        }
        __syncthreads();            // G complete before gemm2 reads it
        gemm_frag(&sm[OFF_V], g_wF + WF_M2 + jt * 36864, 6, nj, lane, mi, acc2);
        __syncthreads();            // G consumed before next jt overwrites
    }

    // ---- residual + staged scatter (3 chunks of 64 cols via P) ----
    {
        for (int ch = 0; ch < 3; ch++) {
            #pragma unroll
            for (int s = 0; s < 2; s++) {
                const int row = mi * 32 + s * 16 + gr;
                #pragma unroll
                for (int n = 0; n < 4; n++) {
                    const int col = nj * 32 + n * 8 + 2 * tg;
                    if ((col >> 6) == ch) {
                        const int cl = col & 63;
                        const float bb0 = __ldg(&bm2[col]);
                        const float bb1 = __ldg(&bm2[col + 1]);
                        sm[OFF_P + cl * SP + row]           = acc2[s][n][0] + bb0 + sm[OFF_X + row * SA + col];
                        sm[OFF_P + (cl + 1) * SP + row]     = acc2[s][n][1] + bb1 + sm[OFF_X + row * SA + col + 1];
                        sm[OFF_P + cl * SP + row + 8]       = acc2[s][n][2] + bb0 + sm[OFF_X + (row + 8) * SA + col];
                        sm[OFF_P + (cl + 1) * SP + row + 8] = acc2[s][n][3] + bb1 + sm[OFF_X + (row + 8) * SA + col + 1];
                    }
                }
            }
            __syncthreads();
            for (int l = tid; l < 1024; l += 384) {
                const int cl  = l >> 4;
                const int r16 = l & 15;
                const int ty  = r16 >> 1, half = r16 & 1;
                const int c   = ch * 64 + cl;
                const int sh  = (hb * 8 + ty + 4) & 255;
                const int sw  = (wb * 8 + half * 4 + 4) & 255;
                const float4 v = *(const float4*)&sm[OFF_P + cl * SP + ty * 8 + half * 4];
                *(float4*)&out[(((size_t)(b * 192 + c)) << 16) + (sh << 8) + sw] = v;
            }
            __syncthreads();
        }
    }
}

extern "C" void kernel_launch(void* const* d_in, const int* in_sizes, int n_in,
                              void* d_out, int out_size)
{
    (void)in_sizes; (void)n_in; (void)out_size;
    const float* x    = (const float*)d_in[0];
    const float* g1   = (const float*)d_in[1];
    const float* b1   = (const float*)d_in[2];
    const float* wqkv = (const float*)d_in[3];
    const float* bqkv = (const float*)d_in[4];
    const float* wo   = (const float*)d_in[5];
    const float* bo   = (const float*)d_in[6];
    const float* g2   = (const float*)d_in[7];
    const float* b2   = (const float*)d_in[8];
    const float* wm1  = (const float*)d_in[9];
    const float* bm1  = (const float*)d_in[10];
    const float* wm2  = (const float*)d_in[11];
    const float* bm2  = (const float*)d_in[12];
    float* out = (float*)d_out;

    cvt_weights<<<(WF_TOTAL + 255) / 256, 256>>>(wqkv, wo, wm1, wm2);
    cudaFuncSetAttribute(swin_block_kernel,
                         cudaFuncAttributeMaxDynamicSharedMemorySize, SMEM_BYTES);
    swin_block_kernel<<<4096, 384, SMEM_BYTES>>>(
        x, g1, b1, bqkv, bo, g2, b2, bm1, bm2, out);
}

// round 15
// speedup vs baseline: 1.4465x; 1.0179x over previous
#include <cuda_runtime.h>
#include <math.h>
#include <stdint.h>

// x: (4,192,256,256) fp32, WS=8, shift=4, NHEADS=4, HD=48, nW=4096, T=64
// 384 threads (12 warps), 1 window/CTA. tf32 mma.sync m16n8k8.
// Weights in MMA-FRAGMENT ORDER (gmem scratch, prologue kernel): 2 LDG.128/kt.
// NEW: activations consumed as GEMM-A (O-concat, LN2 out H, gelu out G) stored
// in FRAGMENT layout in SMEM: one LDS.128 per (kt, m-tile) replaces 4 LDS.32.
// Lane perm (lane*9)&31 keeps consumer LDS.128 conflict-free. X/K/V t-major.
#define SA 196
#define SP 68
#define FU 132           // frag unit stride (128 + 4 pad)
#define OFF_X  0         // X residual (LN1 out), t-major, 12544 f
#define OFF_QF 12544     // Q/O-concat -> H (LN2 out), FRAG layout, 96*132=12672 f
#define OFF_K  25216     // K, t-major, 12544 f
#define OFF_V  37760     // V t-major -> G FRAG (12672 f region)
#define OFF_P  50432     // LN scratch / out staging (4352 f)
#define SMEM_FLOATS 54784
#define SMEM_BYTES (SMEM_FLOATS * 4)   // 219136 B

// fragment-ordered fp32 weight scratch (unchanged from R13/14)
#define WF_QKV 0
#define WF_O   110592
#define WF_M1  147456
#define WF_M2  294912
#define WF_TOTAL 442368
static __device__ __align__(16) float g_wF[WF_TOTAL];

__global__ void cvt_weights(const float* __restrict__ wqkv, const float* __restrict__ wo,
                            const float* __restrict__ wm1,  const float* __restrict__ wm2)
{
    const int i = blockIdx.x * 256 + threadIdx.x;
    if (i >= WF_TOTAL) return;
    const int j    = i & 7;
    const int lane = (i >> 3) & 31;
    const int unit = i >> 8;
    const int sn = j & 3, isb1 = j >> 2;
    const int gr = lane >> 2, tg = lane & 3;
    float v;
    if (i < WF_O) {                                  // qkv: S=18
        const int slab = unit % 18, kt = unit / 18;
        const int k = kt * 8 + tg + isb1 * 4;
        const int col = slab * 32 + sn * 8 + gr;
        v = wqkv[k * 576 + col];
    } else if (i < WF_M1) {                          // o: S=6
        const int u = unit - WF_O / 256;
        const int slab = u % 6, kt = u / 6;
        const int k = kt * 8 + tg + isb1 * 4;
        const int col = slab * 32 + sn * 8 + gr;
        v = wo[k * 192 + col];
    } else if (i < WF_M2) {                          // m1: S=24
        const int u = unit - WF_M1 / 256;
        const int slab = u % 24, kt = u / 24;
        const int k = kt * 8 + tg + isb1 * 4;
        const int col = slab * 32 + sn * 8 + gr;
        v = wm1[k * 768 + col];
    } else {                                         // m2: 4 chunks, S=6
        const int u = unit - WF_M2 / 256;
        const int chunk = u / (24 * 6);
        const int u2 = u - chunk * 24 * 6;
        const int slab = u2 % 6, kt = u2 / 6;
        const int k = kt * 8 + tg + isb1 * 4;
        const int col = slab * 32 + sn * 8 + gr;
        v = wm2[(chunk * 192 + k) * 192 + col];
    }
    g_wF[i] = v;
}

__device__ __forceinline__ void mma_tf32(float (&d)[4],
                                         uint32_t a0, uint32_t a1, uint32_t a2, uint32_t a3,
                                         uint32_t b0, uint32_t b1)
{
    asm volatile(
        "mma.sync.aligned.m16n8k8.row.col.f32.tf32.tf32.f32 "
        "{%0,%1,%2,%3}, {%4,%5,%6,%7}, {%8,%9}, {%0,%1,%2,%3};"
        : "+f"(d[0]), "+f"(d[1]), "+f"(d[2]), "+f"(d[3])
        : "r"(a0), "r"(a1), "r"(a2), "r"(a3), "r"(b0), "r"(b1));
}

// SMEM address of element (token t, channel c) in a fragment-ordered slab
__device__ __forceinline__ int fragAddr(int slab, int t, int c)
{
    const int u = (c >> 3) * 4 + (t >> 4);
    const int L = (t & 7) * 4 + (c & 3);
    const int E = (((c >> 2) & 1) << 1) | ((t >> 3) & 1);
    return slab + u * FU + ((L * 9) & 31) * 4 + E;
}

// GEMM with A from t-major SMEM (scalar A-loads) — used for qkv only (A = X)
__device__ __forceinline__ void gemm_frag(const float* __restrict__ sA,
                                          const float* __restrict__ fragBase,
                                          int S, int slab,
                                          int lane, int mi,
                                          float (&acc)[2][4][4])
{
    const int gr = lane >> 2, tg = lane & 3;
    const float4* fp = (const float4*)(fragBase + ((size_t)slab * 32 + lane) * 8);
    const int step4 = S * 64;
    const float* A0 = sA + (mi * 32 + gr) * SA + tg;
    #pragma unroll 4
    for (int kt = 0; kt < 24; kt++) {
        const float4 q0 = __ldg(fp);
        const float4 q1 = __ldg(fp + 1);
        fp += step4;
        const uint32_t b0[4] = {__float_as_uint(q0.x), __float_as_uint(q0.y),
                                __float_as_uint(q0.z), __float_as_uint(q0.w)};
        const uint32_t b1[4] = {__float_as_uint(q1.x), __float_as_uint(q1.y),
                                __float_as_uint(q1.z), __float_as_uint(q1.w)};
        #pragma unroll
        for (int s = 0; s < 2; s++) {
            const float* Ab = A0 + s * 16 * SA + kt * 8;
            const uint32_t a0 = __float_as_uint(Ab[0]);
            const uint32_t a1 = __float_as_uint(Ab[8 * SA]);
            const uint32_t a2 = __float_as_uint(Ab[4]);
            const uint32_t a3 = __float_as_uint(Ab[8 * SA + 4]);
            #pragma unroll
            for (int sn = 0; sn < 4; sn++)
                mma_tf32(acc[s][sn], a0, a1, a2, a3, b0[sn], b1[sn]);
        }
    }
}

// GEMM with A from FRAGMENT-ordered SMEM: one LDS.128 per (kt, m-tile)
__device__ __forceinline__ void gemm_fragA(const float* __restrict__ sm,
                                           int slabA,
                                           const float* __restrict__ fragBase,
                                           int S, int slab,
                                           int lane, int mi,
                                           float (&acc)[2][4][4])
{
    const float4* fp = (const float4*)(fragBase + ((size_t)slab * 32 + lane) * 8);
    const int step4 = S * 64;
    const int perm4 = ((lane * 9) & 31) * 4;
    #pragma unroll 4
    for (int kt = 0; kt < 24; kt++) {
        const float4 q0 = __ldg(fp);
        const float4 q1 = __ldg(fp + 1);
        fp += step4;
        const uint32_t b0[4] = {__float_as_uint(q0.x), __float_as_uint(q0.y),
                                __float_as_uint(q0.z), __float_as_uint(q0.w)};
        const uint32_t b1[4] = {__float_as_uint(q1.x), __float_as_uint(q1.y),
                                __float_as_uint(q1.z), __float_as_uint(q1.w)};
        #pragma unroll
        for (int s = 0; s < 2; s++) {
            const float4 av = *(const float4*)&sm[slabA + (kt * 4 + mi * 2 + s) * FU + perm4];
            const uint32_t a0 = __float_as_uint(av.x);
            const uint32_t a1 = __float_as_uint(av.y);
            const uint32_t a2 = __float_as_uint(av.z);
            const uint32_t a3 = __float_as_uint(av.w);
            #pragma unroll
            for (int sn = 0; sn < 4; sn++)
                mma_tf32(acc[s][sn], a0, a1, a2, a3, b0[sn], b1[sn]);
        }
    }
}

// token-parallel LayerNorm, t-major src -> t-major dst
__device__ __forceinline__ void layernorm(float* __restrict__ sm,
                                          int src, int dst,
                                          const float* __restrict__ g,
                                          const float* __restrict__ bp,
                                          int tid)
{
    __syncthreads();
    const int t = tid & 63, chk = tid >> 6;
    {
        const float* row = &sm[src + t * SA + chk * 32];
        float s = 0.f, s2 = 0.f;
        #pragma unroll
        for (int j4 = 0; j4 < 8; j4++) {
            const float4 v = *(const float4*)&row[j4 * 4];
            s  += v.x + v.y + v.z + v.w;
            s2 += v.x * v.x + v.y * v.y + v.z * v.z + v.w * v.w;
        }
        sm[OFF_P + chk * 64 + t]       = s;
        sm[OFF_P + 384 + chk * 64 + t] = s2;
    }
    __syncthreads();
    if (tid < 64) {
        float s = 0.f, s2 = 0.f;
        #pragma unroll
        for (int ch = 0; ch < 6; ch++) {
            s  += sm[OFF_P + ch * 64 + tid];
            s2 += sm[OFF_P + 384 + ch * 64 + tid];
        }
        const float mean = s * (1.f / 192.f);
        const float var  = s2 * (1.f / 192.f) - mean * mean;
        sm[OFF_P + 768 + tid] = mean;
        sm[OFF_P + 832 + tid] = rsqrtf(var + 1e-5f);
    }
    __syncthreads();
    {
        const float mean = sm[OFF_P + 768 + t];
        const float rstd = sm[OFF_P + 832 + t];
        const float* row = &sm[src + t * SA + chk * 32];
        float* drow = &sm[dst + t * SA + chk * 32];
        #pragma unroll
        for (int j4 = 0; j4 < 8; j4++) {
            float4 v = *(const float4*)&row[j4 * 4];
            const float4 gg = *(const float4*)&g[chk * 32 + j4 * 4];
            const float4 bb = *(const float4*)&bp[chk * 32 + j4 * 4];
            v.x = (v.x - mean) * rstd * gg.x + bb.x;
            v.y = (v.y - mean) * rstd * gg.y + bb.y;
            v.z = (v.z - mean) * rstd * gg.z + bb.z;
            v.w = (v.w - mean) * rstd * gg.w + bb.w;
            *(float4*)&drow[j4 * 4] = v;
        }
    }
    __syncthreads();
}

// token-parallel LayerNorm, t-major src -> FRAGMENT-ordered dst
__device__ __forceinline__ void layernorm_frag(float* __restrict__ sm,
                                               int src, int dstFrag,
                                               const float* __restrict__ g,
                                               const float* __restrict__ bp,
                                               int tid)
{
    __syncthreads();
    const int t = tid & 63, chk = tid >> 6;
    {
        const float* row = &sm[src + t * SA + chk * 32];
        float s = 0.f, s2 = 0.f;
        #pragma unroll
        for (int j4 = 0; j4 < 8; j4++) {
            const float4 v = *(const float4*)&row[j4 * 4];
            s  += v.x + v.y + v.z + v.w;
            s2 += v.x * v.x + v.y * v.y + v.z * v.z + v.w * v.w;
        }
        sm[OFF_P + chk * 64 + t]       = s;
        sm[OFF_P + 384 + chk * 64 + t] = s2;
    }
    __syncthreads();
    if (tid < 64) {
        float s = 0.f, s2 = 0.f;
        #pragma unroll
        for (int ch = 0; ch < 6; ch++) {
            s  += sm[OFF_P + ch * 64 + tid];
            s2 += sm[OFF_P + 384 + ch * 64 + tid];
        }
        const float mean = s * (1.f / 192.f);
        const float var  = s2 * (1.f / 192.f) - mean * mean;
        sm[OFF_P + 768 + tid] = mean;
        sm[OFF_P + 832 + tid] = rsqrtf(var + 1e-5f);
    }
    __syncthreads();
    {
        const float mean = sm[OFF_P + 768 + t];
        const float rstd = sm[OFF_P + 832 + t];
        const float* row = &sm[src + t * SA + chk * 32];
        #pragma unroll
        for (int j4 = 0; j4 < 8; j4++) {
            float4 v = *(const float4*)&row[j4 * 4];
            const float4 gg = *(const float4*)&g[chk * 32 + j4 * 4];
            const float4 bb = *(const float4*)&bp[chk * 32 + j4 * 4];
            v.x = (v.x - mean) * rstd * gg.x + bb.x;
            v.y = (v.y - mean) * rstd * gg.y + bb.y;
            v.z = (v.z - mean) * rstd * gg.z + bb.z;
            v.w = (v.w - mean) * rstd * gg.w + bb.w;
            const int c0 = chk * 32 + j4 * 4;
            sm[fragAddr(dstFrag, t, c0)]     = v.x;
            sm[fragAddr(dstFrag, t, c0 + 1)] = v.y;
            sm[fragAddr(dstFrag, t, c0 + 2)] = v.z;
            sm[fragAddr(dstFrag, t, c0 + 3)] = v.w;
        }
    }
    __syncthreads();
}

__global__ __launch_bounds__(384, 1)
void swin_block_kernel(const float* __restrict__ x,
                       const float* __restrict__ g1,  const float* __restrict__ b1,
                       const float* __restrict__ bqkv,
                       const float* __restrict__ bo,
                       const float* __restrict__ g2,  const float* __restrict__ b2,
                       const float* __restrict__ bm1, const float* __restrict__ bm2,
                       float* __restrict__ out)
{
    extern __shared__ float sm[];
    const int tid  = threadIdx.x;
    const int wid  = tid >> 5;
    const int lane = tid & 31;
    const int gr   = lane >> 2, tg = lane & 3;
    const int mi   = wid & 1;               // 2 m-tiles of 32 rows
    const int nj   = wid >> 1;              // 6 n-tiles of 32 cols
    const int wi   = blockIdx.x;
    const int b    = wi >> 10;
    const int hb   = (wi >> 5) & 31;
    const int wb   = wi & 31;

    // ---- gather window into X (t-major), shift folded, coalesced gmem float4 ----
    for (int l = tid; l < 3072; l += 384) {
        const int c    = l >> 4;
        const int r16  = l & 15;
        const int ty   = r16 >> 1, half = r16 & 1;
        const int sh   = (hb * 8 + ty + 4) & 255;
        const int sw   = (wb * 8 + half * 4 + 4) & 255;
        const float4 v = *(const float4*)&x[(((size_t)(b * 192 + c)) << 16) + (sh << 8) + sw];
        const int t0 = ty * 8 + half * 4;
        sm[OFF_X + (t0 + 0) * SA + c] = v.x;
        sm[OFF_X + (t0 + 1) * SA + c] = v.y;
        sm[OFF_X + (t0 + 2) * SA + c] = v.z;
        sm[OFF_X + (t0 + 3) * SA + c] = v.w;
    }

    // ---- LN1 in place (residual base = LN1 output) ----
    layernorm(sm, OFF_X, OFF_X, g1, b1, tid);

    // ---- q / k / v GEMMs (A = X t-major; Q written FRAG, K/V t-major) ----
    #pragma unroll 1
    for (int p = 0; p < 3; p++) {
        float acc[2][4][4];
        #pragma unroll
        for (int s = 0; s < 2; s++)
            #pragma unroll
            for (int n = 0; n < 4; n++)
                #pragma unroll
                for (int r = 0; r < 4; r++) acc[s][n][r] = 0.f;
        gemm_frag(&sm[OFF_X], g_wF + WF_QKV, 18, p * 6 + nj, lane, mi, acc);
        #pragma unroll
        for (int s = 0; s < 2; s++) {
            const int row = mi * 32 + s * 16 + gr;
            #pragma unroll
            for (int n = 0; n < 4; n++) {
                const int col = nj * 32 + n * 8 + 2 * tg;
                const float bb0 = __ldg(&bqkv[p * 192 + col]);
                const float bb1 = __ldg(&bqkv[p * 192 + col + 1]);
                if (p == 0) {
                    sm[fragAddr(OFF_QF, row,     col)]     = acc[s][n][0] + bb0;
                    sm[fragAddr(OFF_QF, row,     col + 1)] = acc[s][n][1] + bb1;
                    sm[fragAddr(OFF_QF, row + 8, col)]     = acc[s][n][2] + bb0;
                    sm[fragAddr(OFF_QF, row + 8, col + 1)] = acc[s][n][3] + bb1;
                } else {
                    float* dst = &sm[(p == 1) ? OFF_K : OFF_V];
                    dst[row * SA + col]           = acc[s][n][0] + bb0;
                    dst[row * SA + col + 1]       = acc[s][n][1] + bb1;
                    dst[(row + 8) * SA + col]     = acc[s][n][2] + bb0;
                    dst[(row + 8) * SA + col + 1] = acc[s][n][3] + bb1;
                }
            }
        }
    }
    __syncthreads();

    // ---- attention: 16 warp-tasks (head h, 16-row tile mi2); ZERO barriers ----
    const float scale = 0.14433756729740643f;     // 1/sqrt(48)
    const int perm4 = ((lane * 9) & 31) * 4;
    for (int task = wid; task < 16; task += 12) {
        const int h = task >> 2, mi2 = task & 3;
        float sc[8][4];
        #pragma unroll
        for (int ni = 0; ni < 8; ni++)
            #pragma unroll
            for (int r = 0; r < 4; r++) sc[ni][r] = 0.f;
        {
            const float* Bb = &sm[OFF_K + gr * SA + h * 48 + tg];
            #pragma unroll
            for (int k8 = 0; k8 < 6; k8++) {
                const float4 av = *(const float4*)&sm[OFF_QF + ((h * 6 + k8) * 4 + mi2) * FU + perm4];
                const uint32_t a0 = __float_as_uint(av.x);
                const uint32_t a1 = __float_as_uint(av.y);
                const uint32_t a2 = __float_as_uint(av.z);
                const uint32_t a3 = __float_as_uint(av.w);
                #pragma unroll
                for (int ni = 0; ni < 8; ni++) {
                    const uint32_t b0 = __float_as_uint(Bb[ni * 8 * SA + k8 * 8]);
                    const uint32_t b1 = __float_as_uint(Bb[ni * 8 * SA + k8 * 8 + 4]);
                    mma_tf32(sc[ni], a0, a1, a2, a3, b0, b1);
                }
            }
        }
        // in-register softmax over 64 cols
        {
            float m0 = -1e30f, m1 = -1e30f;
            #pragma unroll
            for (int ni = 0; ni < 8; ni++) {
                #pragma unroll
                for (int r = 0; r < 4; r++) sc[ni][r] *= scale;
                m0 = fmaxf(m0, fmaxf(sc[ni][0], sc[ni][1]));
                m1 = fmaxf(m1, fmaxf(sc[ni][2], sc[ni][3]));
            }
            m0 = fmaxf(m0, __shfl_xor_sync(0xffffffffu, m0, 1));
            m0 = fmaxf(m0, __shfl_xor_sync(0xffffffffu, m0, 2));
            m1 = fmaxf(m1, __shfl_xor_sync(0xffffffffu, m1, 1));
            m1 = fmaxf(m1, __shfl_xor_sync(0xffffffffu, m1, 2));
            float s0 = 0.f, s1 = 0.f;
            #pragma unroll
            for (int ni = 0; ni < 8; ni++) {
                sc[ni][0] = __expf(sc[ni][0] - m0);
                sc[ni][1] = __expf(sc[ni][1] - m0);
                sc[ni][2] = __expf(sc[ni][2] - m1);
                sc[ni][3] = __expf(sc[ni][3] - m1);
                s0 += sc[ni][0] + sc[ni][1];
                s1 += sc[ni][2] + sc[ni][3];
            }
            s0 += __shfl_xor_sync(0xffffffffu, s0, 1);
            s0 += __shfl_xor_sync(0xffffffffu, s0, 2);
            s1 += __shfl_xor_sync(0xffffffffu, s1, 1);
            s1 += __shfl_xor_sync(0xffffffffu, s1, 2);
            const float i0 = 1.f / s0, i1 = 1.f / s1;
            #pragma unroll
            for (int ni = 0; ni < 8; ni++) {
                sc[ni][0] *= i0; sc[ni][1] *= i0;
                sc[ni][2] *= i1; sc[ni][3] *= i1;
            }
        }
        // AV with shfl-transposed A-frags; O written FRAG into QF
        {
            float ao[6][4];
            #pragma unroll
            for (int ci = 0; ci < 6; ci++)
                #pragma unroll
                for (int r = 0; r < 4; r++) ao[ci][r] = 0.f;
            const int sl0 = gr * 4 + (tg >> 1);
            const int sl1 = sl0 + 2;
            const int odd = tg & 1;
            const float* Vb = &sm[OFF_V + tg * SA + h * 48 + gr];
            #pragma unroll
            for (int kk = 0; kk < 8; kk++) {
                const float t00 = __shfl_sync(0xffffffffu, sc[kk][0], sl0);
                const float t01 = __shfl_sync(0xffffffffu, sc[kk][1], sl0);
                const float t20 = __shfl_sync(0xffffffffu, sc[kk][0], sl1);
                const float t21 = __shfl_sync(0xffffffffu, sc[kk][1], sl1);
                const float t10 = __shfl_sync(0xffffffffu, sc[kk][2], sl0);
                const float t11 = __shfl_sync(0xffffffffu, sc[kk][3], sl0);
                const float t30 = __shfl_sync(0xffffffffu, sc[kk][2], sl1);
                const float t31 = __shfl_sync(0xffffffffu, sc[kk][3], sl1);
                const uint32_t a0 = __float_as_uint(odd ? t01 : t00);
                const uint32_t a2 = __float_as_uint(odd ? t21 : t20);
                const uint32_t a1 = __float_as_uint(odd ? t11 : t10);
                const uint32_t a3 = __float_as_uint(odd ? t31 : t30);
                #pragma unroll
                for (int ci = 0; ci < 6; ci++) {
                    const uint32_t b0 = __float_as_uint(Vb[(kk * 8) * SA + ci * 8]);
                    const uint32_t b1 = __float_as_uint(Vb[(kk * 8 + 4) * SA + ci * 8]);
                    mma_tf32(ao[ci], a0, a1, a2, a3, b0, b1);
                }
            }
            const int row = mi2 * 16 + gr;
            #pragma unroll
            for (int ci = 0; ci < 6; ci++) {
                const int col = h * 48 + ci * 8 + 2 * tg;
                sm[fragAddr(OFF_QF, row,     col)]     = ao[ci][0];
                sm[fragAddr(OFF_QF, row,     col + 1)] = ao[ci][1];
                sm[fragAddr(OFF_QF, row + 8, col)]     = ao[ci][2];
                sm[fragAddr(OFF_QF, row + 8, col + 1)] = ao[ci][3];
            }
        }
    }
    __syncthreads();

    // ---- o-proj (A = O-concat FRAG) + residual RMW into X ----
    {
        float acc[2][4][4];
        #pragma unroll
        for (int s = 0; s < 2; s++)
            #pragma unroll
            for (int n = 0; n < 4; n++)
                #pragma unroll
                for (int r = 0; r < 4; r++) acc[s][n][r] = 0.f;
        gemm_fragA(sm, OFF_QF, g_wF + WF_O, 6, nj, lane, mi, acc);
        #pragma unroll
        for (int s = 0; s < 2; s++) {
            const int row = mi * 32 + s * 16 + gr;
            #pragma unroll
            for (int n = 0; n < 4; n++) {
                const int col = nj * 32 + n * 8 + 2 * tg;
                const float bb0 = __ldg(&bo[col]);
                const float bb1 = __ldg(&bo[col + 1]);
                sm[OFF_X + row * SA + col]           += acc[s][n][0] + bb0;
                sm[OFF_X + row * SA + col + 1]       += acc[s][n][1] + bb1;
                sm[OFF_X + (row + 8) * SA + col]     += acc[s][n][2] + bb0;
                sm[OFF_X + (row + 8) * SA + col + 1] += acc[s][n][3] + bb1;
            }
        }
    }

    // ---- LN2: X -> H (FRAG, reuses QF slab; Q dead after o-proj) ----
    layernorm_frag(sm, OFF_X, OFF_QF, g2, b2, tid);

    // ---- MLP: 4 hidden slabs of 192; G FRAG in V slab ----
    float acc2[2][4][4];
    #pragma unroll
    for (int s = 0; s < 2; s++)
        #pragma unroll
        for (int n = 0; n < 4; n++)
            #pragma unroll
            for (int r = 0; r < 4; r++) acc2[s][n][r] = 0.f;

    #pragma unroll 1
    for (int jt = 0; jt < 4; jt++) {
        float acc1[2][4][4];
        #pragma unroll
        for (int s = 0; s < 2; s++)
            #pragma unroll
            for (int n = 0; n < 4; n++)
                #pragma unroll
                for (int r = 0; r < 4; r++) acc1[s][n][r] = 0.f;
        gemm_fragA(sm, OFF_QF, g_wF + WF_M1, 24, jt * 6 + nj, lane, mi, acc1);
        #pragma unroll
        for (int s = 0; s < 2; s++) {
            const int row = mi * 32 + s * 16 + gr;
            #pragma unroll
            for (int n = 0; n < 4; n++) {
                const int col = nj * 32 + n * 8 + 2 * tg;
                const float bb0 = __ldg(&bm1[jt * 192 + col]);
                const float bb1 = __ldg(&bm1[jt * 192 + col + 1]);
                float v0 = acc1[s][n][0] + bb0, v1 = acc1[s][n][1] + bb1;
                float v2 = acc1[s][n][2] + bb0, v3 = acc1[s][n][3] + bb1;
                v0 = 0.5f * v0 * (1.f + erff(v0 * 0.70710678118654752f));
                v1 = 0.5f * v1 * (1.f + erff(v1 * 0.70710678118654752f));
                v2 = 0.5f * v2 * (1.f + erff(v2 * 0.70710678118654752f));
                v3 = 0.5f * v3 * (1.f + erff(v3 * 0.70710678118654752f));
                sm[fragAddr(OFF_V, row,     col)]     = v0;
                sm[fragAddr(OFF_V, row,     col + 1)] = v1;
                sm[fragAddr(OFF_V, row + 8, col)]     = v2;
                sm[fragAddr(OFF_V, row + 8, col + 1)] = v3;
            }
        }
        __syncthreads();            // G complete before gemm2 reads it
        gemm_fragA(sm, OFF_V, g_wF + WF_M2 + jt * 36864, 6, nj, lane, mi, acc2);
        __syncthreads();            // G consumed before next jt overwrites
    }

    // ---- residual + staged scatter (3 chunks of 64 cols via P) ----
    {
        for (int ch = 0; ch < 3; ch++) {
            #pragma unroll
            for (int s = 0; s < 2; s++) {
                const int row = mi * 32 + s * 16 + gr;
                #pragma unroll
                for (int n = 0; n < 4; n++) {
                    const int col = nj * 32 + n * 8 + 2 * tg;
                    if ((col >> 6) == ch) {
                        const int cl = col & 63;
                        const float bb0 = __ldg(&bm2[col]);
                        const float bb1 = __ldg(&bm2[col + 1]);
                        sm[OFF_P + cl * SP + row]           = acc2[s][n][0] + bb0 + sm[OFF_X + row * SA + col];
                        sm[OFF_P + (cl + 1) * SP + row]     = acc2[s][n][1] + bb1 + sm[OFF_X + row * SA + col + 1];
                        sm[OFF_P + cl * SP + row + 8]       = acc2[s][n][2] + bb0 + sm[OFF_X + (row + 8) * SA + col];
                        sm[OFF_P + (cl + 1) * SP + row + 8] = acc2[s][n][3] + bb1 + sm[OFF_X + (row + 8) * SA + col + 1];
                    }
                }
            }
            __syncthreads();
            for (int l = tid; l < 1024; l += 384) {
                const int cl  = l >> 4;
                const int r16 = l & 15;
                const int ty  = r16 >> 1, half = r16 & 1;
                const int c   = ch * 64 + cl;
                const int sh  = (hb * 8 + ty + 4) & 255;
                const int sw  = (wb * 8 + half * 4 + 4) & 255;
                const float4 v = *(const float4*)&sm[OFF_P + cl * SP + ty * 8 + half * 4];
                *(float4*)&out[(((size_t)(b * 192 + c)) << 16) + (sh << 8) + sw] = v;
            }
            __syncthreads();
        }
    }
}

extern "C" void kernel_launch(void* const* d_in, const int* in_sizes, int n_in,
                              void* d_out, int out_size)
{
    (void)in_sizes; (void)n_in; (void)out_size;
    const float* x    = (const float*)d_in[0];
    const float* g1   = (const float*)d_in[1];
    const float* b1   = (const float*)d_in[2];
    const float* wqkv = (const float*)d_in[3];
    const float* bqkv = (const float*)d_in[4];
    const float* wo   = (const float*)d_in[5];
    const float* bo   = (const float*)d_in[6];
    const float* g2   = (const float*)d_in[7];
    const float* b2   = (const float*)d_in[8];
    const float* wm1  = (const float*)d_in[9];
    const float* bm1  = (const float*)d_in[10];
    const float* wm2  = (const float*)d_in[11];
    const float* bm2  = (const float*)d_in[12];
    float* out = (float*)d_out;

    cvt_weights<<<(WF_TOTAL + 255) / 256, 256>>>(wqkv, wo, wm1, wm2);
    cudaFuncSetAttribute(swin_block_kernel,
                         cudaFuncAttributeMaxDynamicSharedMemorySize, SMEM_BYTES);
    swin_block_kernel<<<4096, 384, SMEM_BYTES>>>(
        x, g1, b1, bqkv, bo, g2, b2, bm1, bm2, out);
}

// round 16
// speedup vs baseline: 1.7360x; 1.2001x over previous
#include <cuda_runtime.h>
#include <cuda_bf16.h>
#include <math.h>
#include <stdint.h>

// x: (4,192,256,256) fp32, WS=8, shift=4, NHEADS=4, HD=48, nW=4096, T=64
// 384 threads (12 warps), 1 window/CTA. tf32 mma.sync m16n8k8.
// Weights in MMA-FRAGMENT ORDER as BF16 (gmem scratch): ONE LDG.128 per kt
// delivers all 8 B-values; bf16->fp32 expansion is an exact shift (subset of
// tf32). Activations/residual stay fp32. GEMM-A activations (O-concat, H, G)
// in fragment SMEM layout (LDS.128). Epilogue frag addresses hoisted (affine
// +4*FU per n-step). X/K/V t-major stride 196.
#define SA 196
#define SP 68
#define FU 132           // frag unit stride (128 + 4 pad)
#define OFF_X  0         // X residual (LN1 out), t-major, 12544 f
#define OFF_QF 12544     // Q/O-concat -> H (LN2 out), FRAG layout, 96*132=12672 f
#define OFF_K  25216     // K, t-major, 12544 f
#define OFF_V  37760     // V t-major -> G FRAG (12672 f region)
#define OFF_P  50432     // LN scratch / out staging (4352 f)
#define SMEM_FLOATS 54784
#define SMEM_BYTES (SMEM_FLOATS * 4)   // 219136 B

// fragment-ordered BF16 weight scratch
// element layout: off + ((kt*S + slab)*32 + lane)*8 + j ; j&3=sn, j>>2=isb1
#define WF_QKV 0
#define WF_O   110592
#define WF_M1  147456
#define WF_M2  294912
#define WF_TOTAL 442368
static __device__ __align__(16) __nv_bfloat16 g_wB[WF_TOTAL];

__global__ void cvt_weights(const float* __restrict__ wqkv, const float* __restrict__ wo,
                            const float* __restrict__ wm1,  const float* __restrict__ wm2)
{
    const int i = blockIdx.x * 256 + threadIdx.x;
    if (i >= WF_TOTAL) return;
    const int j    = i & 7;
    const int lane = (i >> 3) & 31;
    const int unit = i >> 8;
    const int sn = j & 3, isb1 = j >> 2;
    const int gr = lane >> 2, tg = lane & 3;
    float v;
    if (i < WF_O) {                                  // qkv: S=18
        const int slab = unit % 18, kt = unit / 18;
        const int k = kt * 8 + tg + isb1 * 4;
        const int col = slab * 32 + sn * 8 + gr;
        v = wqkv[k * 576 + col];
    } else if (i < WF_M1) {                          // o: S=6
        const int u = unit - WF_O / 256;
        const int slab = u % 6, kt = u / 6;
        const int k = kt * 8 + tg + isb1 * 4;
        const int col = slab * 32 + sn * 8 + gr;
        v = wo[k * 192 + col];
    } else if (i < WF_M2) {                          // m1: S=24
        const int u = unit - WF_M1 / 256;
        const int slab = u % 24, kt = u / 24;
        const int k = kt * 8 + tg + isb1 * 4;
        const int col = slab * 32 + sn * 8 + gr;
        v = wm1[k * 768 + col];
    } else {                                         // m2: 4 chunks, S=6
        const int u = unit - WF_M2 / 256;
        const int chunk = u / (24 * 6);
        const int u2 = u - chunk * 24 * 6;
        const int slab = u2 % 6, kt = u2 / 6;
        const int k = kt * 8 + tg + isb1 * 4;
        const int col = slab * 32 + sn * 8 + gr;
        v = wm2[(chunk * 192 + k) * 192 + col];
    }
    g_wB[i] = __float2bfloat16(v);
}

__device__ __forceinline__ void mma_tf32(float (&d)[4],
                                         uint32_t a0, uint32_t a1, uint32_t a2, uint32_t a3,
                                         uint32_t b0, uint32_t b1)
{
    asm volatile(
        "mma.sync.aligned.m16n8k8.row.col.f32.tf32.tf32.f32 "
        "{%0,%1,%2,%3}, {%4,%5,%6,%7}, {%8,%9}, {%0,%1,%2,%3};"
        : "+f"(d[0]), "+f"(d[1]), "+f"(d[2]), "+f"(d[3])
        : "r"(a0), "r"(a1), "r"(a2), "r"(a3), "r"(b0), "r"(b1));
}

// expand one uint4 of 8 bf16 B-values into b0[4], b1[4] (exact: bf16<<16)
__device__ __forceinline__ void expand_b(const uint4 q, uint32_t (&b0)[4], uint32_t (&b1)[4])
{
    b0[0] = q.x << 16; b0[1] = q.x & 0xFFFF0000u;
    b0[2] = q.y << 16; b0[3] = q.y & 0xFFFF0000u;
    b1[0] = q.z << 16; b1[1] = q.z & 0xFFFF0000u;
    b1[2] = q.w << 16; b1[3] = q.w & 0xFFFF0000u;
}

// SMEM address of element (token t, channel c) in a fragment-ordered slab
__device__ __forceinline__ int fragAddr(int slab, int t, int c)
{
    const int u = (c >> 3) * 4 + (t >> 4);
    const int L = (t & 7) * 4 + (c & 3);
    const int E = (((c >> 2) & 1) << 1) | ((t >> 3) & 1);
    return slab + u * FU + ((L * 9) & 31) * 4 + E;
}

// GEMM with A from t-major SMEM — used for qkv only (A = X)
__device__ __forceinline__ void gemm_frag(const float* __restrict__ sA,
                                          const __nv_bfloat16* __restrict__ fragBase,
                                          int S, int slab,
                                          int lane, int mi,
                                          float (&acc)[2][4][4])
{
    const int gr = lane >> 2, tg = lane & 3;
    const uint4* fp = (const uint4*)fragBase + (size_t)slab * 32 + lane;
    const int stepU = S * 32;
    const float* A0 = sA + (mi * 32 + gr) * SA + tg;
    #pragma unroll 4
    for (int kt = 0; kt < 24; kt++) {
        const uint4 q = __ldg(fp);
        fp += stepU;
        uint32_t b0[4], b1[4];
        expand_b(q, b0, b1);
        #pragma unroll
        for (int s = 0; s < 2; s++) {
            const float* Ab = A0 + s * 16 * SA + kt * 8;
            const uint32_t a0 = __float_as_uint(Ab[0]);
            const uint32_t a1 = __float_as_uint(Ab[8 * SA]);
            const uint32_t a2 = __float_as_uint(Ab[4]);
            const uint32_t a3 = __float_as_uint(Ab[8 * SA + 4]);
            #pragma unroll
            for (int sn = 0; sn < 4; sn++)
                mma_tf32(acc[s][sn], a0, a1, a2, a3, b0[sn], b1[sn]);
        }
    }
}

// GEMM with A from FRAGMENT-ordered SMEM: one LDS.128 per (kt, m-tile)
__device__ __forceinline__ void gemm_fragA(const float* __restrict__ sm,
                                           int slabA,
                                           const __nv_bfloat16* __restrict__ fragBase,
                                           int S, int slab,
                                           int lane, int mi,
                                           float (&acc)[2][4][4])
{
    const uint4* fp = (const uint4*)fragBase + (size_t)slab * 32 + lane;
    const int stepU = S * 32;
    const int perm4 = ((lane * 9) & 31) * 4;
    #pragma unroll 4
    for (int kt = 0; kt < 24; kt++) {
        const uint4 q = __ldg(fp);
        fp += stepU;
        uint32_t b0[4], b1[4];
        expand_b(q, b0, b1);
        #pragma unroll
        for (int s = 0; s < 2; s++) {
            const float4 av = *(const float4*)&sm[slabA + (kt * 4 + mi * 2 + s) * FU + perm4];
            const uint32_t a0 = __float_as_uint(av.x);
            const uint32_t a1 = __float_as_uint(av.y);
            const uint32_t a2 = __float_as_uint(av.z);
            const uint32_t a3 = __float_as_uint(av.w);
            #pragma unroll
            for (int sn = 0; sn < 4; sn++)
                mma_tf32(acc[s][sn], a0, a1, a2, a3, b0[sn], b1[sn]);
        }
    }
}

// token-parallel LayerNorm, t-major src -> t-major dst
__device__ __forceinline__ void layernorm(float* __restrict__ sm,
                                          int src, int dst,
                                          const float* __restrict__ g,
                                          const float* __restrict__ bp,
                                          int tid)
{
    __syncthreads();
    const int t = tid & 63, chk = tid >> 6;
    {
        const float* row = &sm[src + t * SA + chk * 32];
        float s = 0.f, s2 = 0.f;
        #pragma unroll
        for (int j4 = 0; j4 < 8; j4++) {
            const float4 v = *(const float4*)&row[j4 * 4];
            s  += v.x + v.y + v.z + v.w;
            s2 += v.x * v.x + v.y * v.y + v.z * v.z + v.w * v.w;
        }
        sm[OFF_P + chk * 64 + t]       = s;
        sm[OFF_P + 384 + chk * 64 + t] = s2;
    }
    __syncthreads();
    if (tid < 64) {
        float s = 0.f, s2 = 0.f;
        #pragma unroll
        for (int ch = 0; ch < 6; ch++) {
            s  += sm[OFF_P + ch * 64 + tid];
            s2 += sm[OFF_P + 384 + ch * 64 + tid];
        }
        const float mean = s * (1.f / 192.f);
        const float var  = s2 * (1.f / 192.f) - mean * mean;
        sm[OFF_P + 768 + tid] = mean;
        sm[OFF_P + 832 + tid] = rsqrtf(var + 1e-5f);
    }
    __syncthreads();
    {
        const float mean = sm[OFF_P + 768 + t];
        const float rstd = sm[OFF_P + 832 + t];
        const float* row = &sm[src + t * SA + chk * 32];
        float* drow = &sm[dst + t * SA + chk * 32];
        #pragma unroll
        for (int j4 = 0; j4 < 8; j4++) {
            float4 v = *(const float4*)&row[j4 * 4];
            const float4 gg = *(const float4*)&g[chk * 32 + j4 * 4];
            const float4 bb = *(const float4*)&bp[chk * 32 + j4 * 4];
            v.x = (v.x - mean) * rstd * gg.x + bb.x;
            v.y = (v.y - mean) * rstd * gg.y + bb.y;
            v.z = (v.z - mean) * rstd * gg.z + bb.z;
            v.w = (v.w - mean) * rstd * gg.w + bb.w;
            *(float4*)&drow[j4 * 4] = v;
        }
    }
    __syncthreads();
}

// token-parallel LayerNorm, t-major src -> FRAGMENT-ordered dst (hoisted addrs)
__device__ __forceinline__ void layernorm_frag(float* __restrict__ sm,
                                               int src, int dstFrag,
                                               const float* __restrict__ g,
                                               const float* __restrict__ bp,
                                               int tid)
{
    __syncthreads();
    const int t = tid & 63, chk = tid >> 6;
    {
        const float* row = &sm[src + t * SA + chk * 32];
        float s = 0.f, s2 = 0.f;
        #pragma unroll
        for (int j4 = 0; j4 < 8; j4++) {
            const float4 v = *(const float4*)&row[j4 * 4];
            s  += v.x + v.y + v.z + v.w;
            s2 += v.x * v.x + v.y * v.y + v.z * v.z + v.w * v.w;
        }
        sm[OFF_P + chk * 64 + t]       = s;
        sm[OFF_P + 384 + chk * 64 + t] = s2;
    }
    __syncthreads();
    if (tid < 64) {
        float s = 0.f, s2 = 0.f;
        #pragma unroll
        for (int ch = 0; ch < 6; ch++) {
            s  += sm[OFF_P + ch * 64 + tid];
            s2 += sm[OFF_P + 384 + ch * 64 + tid];
        }
        const float mean = s * (1.f / 192.f);
        const float var  = s2 * (1.f / 192.f) - mean * mean;
        sm[OFF_P + 768 + tid] = mean;
        sm[OFF_P + 832 + tid] = rsqrtf(var + 1e-5f);
    }
    __syncthreads();
    {
        const float mean = sm[OFF_P + 768 + t];
        const float rstd = sm[OFF_P + 832 + t];
        const float* row = &sm[src + t * SA + chk * 32];
        // hoist: addrs for j4=0 and j4=1; j4+2 -> c+=8 -> u+=4 -> +4*FU
        int a0[4], a1[4];
        #pragma unroll
        for (int e = 0; e < 4; e++) {
            a0[e] = fragAddr(dstFrag, t, chk * 32 + e);
            a1[e] = fragAddr(dstFrag, t, chk * 32 + 4 + e);
        }
        #pragma unroll
        for (int j4 = 0; j4 < 8; j4++) {
            float4 v = *(const float4*)&row[j4 * 4];
            const float4 gg = *(const float4*)&g[chk * 32 + j4 * 4];
            const float4 bb = *(const float4*)&bp[chk * 32 + j4 * 4];
            v.x = (v.x - mean) * rstd * gg.x + bb.x;
            v.y = (v.y - mean) * rstd * gg.y + bb.y;
            v.z = (v.z - mean) * rstd * gg.z + bb.z;
            v.w = (v.w - mean) * rstd * gg.w + bb.w;
            const int* ab = (j4 & 1) ? a1 : a0;
            const int off = (j4 >> 1) * 4 * FU;
            sm[ab[0] + off] = v.x;
            sm[ab[1] + off] = v.y;
            sm[ab[2] + off] = v.z;
            sm[ab[3] + off] = v.w;
        }
    }
    __syncthreads();
}

__global__ __launch_bounds__(384, 1)
void swin_block_kernel(const float* __restrict__ x,
                       const float* __restrict__ g1,  const float* __restrict__ b1,
                       const float* __restrict__ bqkv,
                       const float* __restrict__ bo,
                       const float* __restrict__ g2,  const float* __restrict__ b2,
                       const float* __restrict__ bm1, const float* __restrict__ bm2,
                       float* __restrict__ out)
{
    extern __shared__ float sm[];
    const int tid  = threadIdx.x;
    const int wid  = tid >> 5;
    const int lane = tid & 31;
    const int gr   = lane >> 2, tg = lane & 3;
    const int mi   = wid & 1;               // 2 m-tiles of 32 rows
    const int nj   = wid >> 1;              // 6 n-tiles of 32 cols
    const int wi   = blockIdx.x;
    const int b    = wi >> 10;
    const int hb   = (wi >> 5) & 31;
    const int wb   = wi & 31;

    // ---- gather window into X (t-major), shift folded, coalesced gmem float4 ----
    for (int l = tid; l < 3072; l += 384) {
        const int c    = l >> 4;
        const int r16  = l & 15;
        const int ty   = r16 >> 1, half = r16 & 1;
        const int sh   = (hb * 8 + ty + 4) & 255;
        const int sw   = (wb * 8 + half * 4 + 4) & 255;
        const float4 v = *(const float4*)&x[(((size_t)(b * 192 + c)) << 16) + (sh << 8) + sw];
        const int t0 = ty * 8 + half * 4;
        sm[OFF_X + (t0 + 0) * SA + c] = v.x;
        sm[OFF_X + (t0 + 1) * SA + c] = v.y;
        sm[OFF_X + (t0 + 2) * SA + c] = v.z;
        sm[OFF_X + (t0 + 3) * SA + c] = v.w;
    }

    // ---- LN1 in place (residual base = LN1 output) ----
    layernorm(sm, OFF_X, OFF_X, g1, b1, tid);

    // ---- q / k / v GEMMs (A = X t-major; Q written FRAG, K/V t-major) ----
    #pragma unroll 1
    for (int p = 0; p < 3; p++) {
        float acc[2][4][4];
        #pragma unroll
        for (int s = 0; s < 2; s++)
            #pragma unroll
            for (int n = 0; n < 4; n++)
                #pragma unroll
                for (int r = 0; r < 4; r++) acc[s][n][r] = 0.f;
        gemm_frag(&sm[OFF_X], g_wB + WF_QKV, 18, p * 6 + nj, lane, mi, acc);
        #pragma unroll
        for (int s = 0; s < 2; s++) {
            const int row = mi * 32 + s * 16 + gr;
            const int col0 = nj * 32 + 2 * tg;
            int a00 = 0, a01 = 0, a10 = 0, a11 = 0;
            if (p == 0) {
                a00 = fragAddr(OFF_QF, row,     col0);
                a01 = fragAddr(OFF_QF, row,     col0 + 1);
                a10 = fragAddr(OFF_QF, row + 8, col0);
                a11 = fragAddr(OFF_QF, row + 8, col0 + 1);
            }
            #pragma unroll
            for (int n = 0; n < 4; n++) {
                const int col = col0 + n * 8;
                const float bb0 = __ldg(&bqkv[p * 192 + col]);
                const float bb1 = __ldg(&bqkv[p * 192 + col + 1]);
                if (p == 0) {
                    const int off = n * 4 * FU;
                    sm[a00 + off] = acc[s][n][0] + bb0;
                    sm[a01 + off] = acc[s][n][1] + bb1;
                    sm[a10 + off] = acc[s][n][2] + bb0;
                    sm[a11 + off] = acc[s][n][3] + bb1;
                } else {
                    float* dst = &sm[(p == 1) ? OFF_K : OFF_V];
                    dst[row * SA + col]           = acc[s][n][0] + bb0;
                    dst[row * SA + col + 1]       = acc[s][n][1] + bb1;
                    dst[(row + 8) * SA + col]     = acc[s][n][2] + bb0;
                    dst[(row + 8) * SA + col + 1] = acc[s][n][3] + bb1;
                }
            }
        }
    }
    __syncthreads();

    // ---- attention: 16 warp-tasks (head h, 16-row tile mi2); ZERO barriers ----
    const float scale = 0.14433756729740643f;     // 1/sqrt(48)
    const int perm4 = ((lane * 9) & 31) * 4;
    for (int task = wid; task < 16; task += 12) {
        const int h = task >> 2, mi2 = task & 3;
        float sc[8][4];
        #pragma unroll
        for (int ni = 0; ni < 8; ni++)
            #pragma unroll
            for (int r = 0; r < 4; r++) sc[ni][r] = 0.f;
        {
            const float* Bb = &sm[OFF_K + gr * SA + h * 48 + tg];
            #pragma unroll
            for (int k8 = 0; k8 < 6; k8++) {
                const float4 av = *(const float4*)&sm[OFF_QF + ((h * 6 + k8) * 4 + mi2) * FU + perm4];
                const uint32_t a0 = __float_as_uint(av.x);
                const uint32_t a1 = __float_as_uint(av.y);
                const uint32_t a2 = __float_as_uint(av.z);
                const uint32_t a3 = __float_as_uint(av.w);
                #pragma unroll
                for (int ni = 0; ni < 8; ni++) {
                    const uint32_t b0 = __float_as_uint(Bb[ni * 8 * SA + k8 * 8]);
                    const uint32_t b1 = __float_as_uint(Bb[ni * 8 * SA + k8 * 8 + 4]);
                    mma_tf32(sc[ni], a0, a1, a2, a3, b0, b1);
                }
            }
        }
        // in-register softmax over 64 cols
        {
            float m0 = -1e30f, m1 = -1e30f;
            #pragma unroll
            for (int ni = 0; ni < 8; ni++) {
                #pragma unroll
                for (int r = 0; r < 4; r++) sc[ni][r] *= scale;
                m0 = fmaxf(m0, fmaxf(sc[ni][0], sc[ni][1]));
                m1 = fmaxf(m1, fmaxf(sc[ni][2], sc[ni][3]));
            }
            m0 = fmaxf(m0, __shfl_xor_sync(0xffffffffu, m0, 1));
            m0 = fmaxf(m0, __shfl_xor_sync(0xffffffffu, m0, 2));
            m1 = fmaxf(m1, __shfl_xor_sync(0xffffffffu, m1, 1));
            m1 = fmaxf(m1, __shfl_xor_sync(0xffffffffu, m1, 2));
            float s0 = 0.f, s1 = 0.f;
            #pragma unroll
            for (int ni = 0; ni < 8; ni++) {
                sc[ni][0] = __expf(sc[ni][0] - m0);
                sc[ni][1] = __expf(sc[ni][1] - m0);
                sc[ni][2] = __expf(sc[ni][2] - m1);
                sc[ni][3] = __expf(sc[ni][3] - m1);
                s0 += sc[ni][0] + sc[ni][1];
                s1 += sc[ni][2] + sc[ni][3];
            }
            s0 += __shfl_xor_sync(0xffffffffu, s0, 1);
            s0 += __shfl_xor_sync(0xffffffffu, s0, 2);
            s1 += __shfl_xor_sync(0xffffffffu, s1, 1);
            s1 += __shfl_xor_sync(0xffffffffu, s1, 2);
            const float i0 = 1.f / s0, i1 = 1.f / s1;
            #pragma unroll
            for (int ni = 0; ni < 8; ni++) {
                sc[ni][0] *= i0; sc[ni][1] *= i0;
                sc[ni][2] *= i1; sc[ni][3] *= i1;
            }
        }
        // AV with shfl-transposed A-frags; O written FRAG into QF (hoisted addrs)
        {
            float ao[6][4];
            #pragma unroll
            for (int ci = 0; ci < 6; ci++)
                #pragma unroll
                for (int r = 0; r < 4; r++) ao[ci][r] = 0.f;
            const int sl0 = gr * 4 + (tg >> 1);
            const int sl1 = sl0 + 2;
            const int odd = tg & 1;
            const float* Vb = &sm[OFF_V + tg * SA + h * 48 + gr];
            #pragma unroll
            for (int kk = 0; kk < 8; kk++) {
                const float t00 = __shfl_sync(0xffffffffu, sc[kk][0], sl0);
                const float t01 = __shfl_sync(0xffffffffu, sc[kk][1], sl0);
                const float t20 = __shfl_sync(0xffffffffu, sc[kk][0], sl1);
                const float t21 = __shfl_sync(0xffffffffu, sc[kk][1], sl1);
                const float t10 = __shfl_sync(0xffffffffu, sc[kk][2], sl0);
                const float t11 = __shfl_sync(0xffffffffu, sc[kk][3], sl0);
                const float t30 = __shfl_sync(0xffffffffu, sc[kk][2], sl1);
                const float t31 = __shfl_sync(0xffffffffu, sc[kk][3], sl1);
                const uint32_t a0 = __float_as_uint(odd ? t01 : t00);
                const uint32_t a2 = __float_as_uint(odd ? t21 : t20);
                const uint32_t a1 = __float_as_uint(odd ? t11 : t10);
                const uint32_t a3 = __float_as_uint(odd ? t31 : t30);
                #pragma unroll
                for (int ci = 0; ci < 6; ci++) {
                    const uint32_t b0 = __float_as_uint(Vb[(kk * 8) * SA + ci * 8]);
                    const uint32_t b1 = __float_as_uint(Vb[(kk * 8 + 4) * SA + ci * 8]);
                    mma_tf32(ao[ci], a0, a1, a2, a3, b0, b1);
                }
            }
            const int row = mi2 * 16 + gr;
            const int col0 = h * 48 + 2 * tg;
            const int a00 = fragAddr(OFF_QF, row,     col0);
            const int a01 = fragAddr(OFF_QF, row,     col0 + 1);
            const int a10 = fragAddr(OFF_QF, row + 8, col0);
            const int a11 = fragAddr(OFF_QF, row + 8, col0 + 1);
            #pragma unroll
            for (int ci = 0; ci < 6; ci++) {
                const int off = ci * 4 * FU;
                sm[a00 + off] = ao[ci][0];
                sm[a01 + off] = ao[ci][1];
                sm[a10 + off] = ao[ci][2];
                sm[a11 + off] = ao[ci][3];
            }
        }
    }
    __syncthreads();

    // ---- o-proj (A = O-concat FRAG) + residual RMW into X ----
    {
        float acc[2][4][4];
        #pragma unroll
        for (int s = 0; s < 2; s++)
            #pragma unroll
            for (int n = 0; n < 4; n++)
                #pragma unroll
                for (int r = 0; r < 4; r++) acc[s][n][r] = 0.f;
        gemm_fragA(sm, OFF_QF, g_wB + WF_O, 6, nj, lane, mi, acc);
        #pragma unroll
        for (int s = 0; s < 2; s++) {
            const int row = mi * 32 + s * 16 + gr;
            #pragma unroll
            for (int n = 0; n < 4; n++) {
                const int col = nj * 32 + n * 8 + 2 * tg;
                const float bb0 = __ldg(&bo[col]);
                const float bb1 = __ldg(&bo[col + 1]);
                sm[OFF_X + row * SA + col]           += acc[s][n][0] + bb0;
                sm[OFF_X + row * SA + col + 1]       += acc[s][n][1] + bb1;
                sm[OFF_X + (row + 8) * SA + col]     += acc[s][n][2] + bb0;
                sm[OFF_X + (row + 8) * SA + col + 1] += acc[s][n][3] + bb1;
            }
        }
    }

    // ---- LN2: X -> H (FRAG, reuses QF slab) ----
    layernorm_frag(sm, OFF_X, OFF_QF, g2, b2, tid);

    // ---- MLP: 4 hidden slabs of 192; G FRAG in V slab ----
    float acc2[2][4][4];
    #pragma unroll
    for (int s = 0; s < 2; s++)
        #pragma unroll
        for (int n = 0; n < 4; n++)
            #pragma unroll
            for (int r = 0; r < 4; r++) acc2[s][n][r] = 0.f;

    #pragma unroll 1
    for (int jt = 0; jt < 4; jt++) {
        float acc1[2][4][4];
        #pragma unroll
        for (int s = 0; s < 2; s++)
            #pragma unroll
            for (int n = 0; n < 4; n++)
                #pragma unroll
                for (int r = 0; r < 4; r++) acc1[s][n][r] = 0.f;
        gemm_fragA(sm, OFF_QF, g_wB + WF_M1, 24, jt * 6 + nj, lane, mi, acc1);
        #pragma unroll
        for (int s = 0; s < 2; s++) {
            const int row = mi * 32 + s * 16 + gr;
            const int col0 = nj * 32 + 2 * tg;
            const int a00 = fragAddr(OFF_V, row,     col0);
            const int a01 = fragAddr(OFF_V, row,     col0 + 1);
            const int a10 = fragAddr(OFF_V, row + 8, col0);
            const int a11 = fragAddr(OFF_V, row + 8, col0 + 1);
            #pragma unroll
            for (int n = 0; n < 4; n++) {
                const int col = col0 + n * 8;
                const float bb0 = __ldg(&bm1[jt * 192 + col]);
                const float bb1 = __ldg(&bm1[jt * 192 + col + 1]);
                float v0 = acc1[s][n][0] + bb0, v1 = acc1[s][n][1] + bb1;
                float v2 = acc1[s][n][2] + bb0, v3 = acc1[s][n][3] + bb1;
                v0 = 0.5f * v0 * (1.f + erff(v0 * 0.70710678118654752f));
                v1 = 0.5f * v1 * (1.f + erff(v1 * 0.70710678118654752f));
                v2 = 0.5f * v2 * (1.f + erff(v2 * 0.70710678118654752f));
                v3 = 0.5f * v3 * (1.f + erff(v3 * 0.70710678118654752f));
                const int off = n * 4 * FU;
                sm[a00 + off] = v0;
                sm[a01 + off] = v1;
                sm[a10 + off] = v2;
                sm[a11 + off] = v3;
            }
        }
        __syncthreads();            // G complete before gemm2 reads it
        gemm_fragA(sm, OFF_V, g_wB + WF_M2 + jt * 36864, 6, nj, lane, mi, acc2);
        __syncthreads();            // G consumed before next jt overwrites
    }

    // ---- residual + staged scatter (3 chunks of 64 cols via P) ----
    {
        for (int ch = 0; ch < 3; ch++) {
            #pragma unroll
            for (int s = 0; s < 2; s++) {
                const int row = mi * 32 + s * 16 + gr;
                #pragma unroll
                for (int n = 0; n < 4; n++) {
                    const int col = nj * 32 + n * 8 + 2 * tg;
                    if ((col >> 6) == ch) {
                        const int cl = col & 63;
                        const float bb0 = __ldg(&bm2[col]);
                        const float bb1 = __ldg(&bm2[col + 1]);
                        sm[OFF_P + cl * SP + row]           = acc2[s][n][0] + bb0 + sm[OFF_X + row * SA + col];
                        sm[OFF_P + (cl + 1) * SP + row]     = acc2[s][n][1] + bb1 + sm[OFF_X + row * SA + col + 1];
                        sm[OFF_P + cl * SP + row + 8]       = acc2[s][n][2] + bb0 + sm[OFF_X + (row + 8) * SA + col];
                        sm[OFF_P + (cl + 1) * SP + row + 8] = acc2[s][n][3] + bb1 + sm[OFF_X + (row + 8) * SA + col + 1];
                    }
                }
            }
            __syncthreads();
            for (int l = tid; l < 1024; l += 384) {
                const int cl  = l >> 4;
                const int r16 = l & 15;
                const int ty  = r16 >> 1, half = r16 & 1;
                const int c   = ch * 64 + cl;
                const int sh  = (hb * 8 + ty + 4) & 255;
                const int sw  = (wb * 8 + half * 4 + 4) & 255;
                const float4 v = *(const float4*)&sm[OFF_P + cl * SP + ty * 8 + half * 4];
                *(float4*)&out[(((size_t)(b * 192 + c)) << 16) + (sh << 8) + sw] = v;
            }
            __syncthreads();
        }
    }
}

extern "C" void kernel_launch(void* const* d_in, const int* in_sizes, int n_in,
                              void* d_out, int out_size)
{
    (void)in_sizes; (void)n_in; (void)out_size;
    const float* x    = (const float*)d_in[0];
    const float* g1   = (const float*)d_in[1];
    const float* b1   = (const float*)d_in[2];
    const float* wqkv = (const float*)d_in[3];
    const float* bqkv = (const float*)d_in[4];
    const float* wo   = (const float*)d_in[5];
    const float* bo   = (const float*)d_in[6];
    const float* g2   = (const float*)d_in[7];
    const float* b2   = (const float*)d_in[8];
    const float* wm1  = (const float*)d_in[9];
    const float* bm1  = (const float*)d_in[10];
    const float* wm2  = (const float*)d_in[11];
    const float* bm2  = (const float*)d_in[12];
    float* out = (float*)d_out;

    cvt_weights<<<(WF_TOTAL + 255) / 256, 256>>>(wqkv, wo, wm1, wm2);
    cudaFuncSetAttribute(swin_block_kernel,
                         cudaFuncAttributeMaxDynamicSharedMemorySize, SMEM_BYTES);
    swin_block_kernel<<<4096, 384, SMEM_BYTES>>>(
        x, g1, b1, bqkv, bo, g2, b2, bm1, bm2, out);
}

// round 17
// speedup vs baseline: 2.2475x; 1.2947x over previous
#include <cuda_runtime.h>
#include <cuda_bf16.h>
#include <math.h>
#include <stdint.h>

// x: (4,192,256,256) fp32, WS=8, shift=4, NHEADS=4, HD=48, nW=4096, T=64
// 384 threads (12 warps), 1 window/CTA. bf16 mma.sync m16n8k16 everywhere,
// fp32 accumulate. Weights in k16 B-FRAGMENT order as bf16 (gmem scratch):
// 2 LDG.128 per kt16 feed 4 n-slabs. Activations consumed by GEMMs stored as
// bf16 A-FRAGMENTS in SMEM (1 LDS.128 per kt16/m-tile, lane-perm l^((l>>3)&3)
// conflict-free). K/V stored as bf16 B-fragments (LDS.64). P(softmax, fp32 in
// regs) packs DIRECTLY into AV A-frags (accumulator layout match, no shfl).
// X residual + LN/softmax/gelu/epilogues all fp32.
#define SA 196
#define SP 68
#define OFF_X  0         // X residual fp32 t-major, 12544 f
#define OFF_XF 12544     // LN1 out bf16 A-frag -> G (gelu out), 6144 f
#define OFF_QF 18688     // Q bf16 A-frag -> O -> H (LN2 out), 6144 f
#define OFF_K  24832     // K bf16 B-frag (channel-k, token-col), 6144 f
#define OFF_V  30976     // V bf16 B-frag (token-k, channel-col), 6144 f
#define OFF_P  37120     // LN scratch / out staging fp32, 4352 f
#define SMEM_FLOATS 41472
#define SMEM_BYTES (SMEM_FLOATS * 4)   // 165888 B

// bf16 k16-fragment weight scratch: ((kt*S + slab)*32 + lane)*16 + j
// j: sn=j>>2 (n-slab), rr=(j>>1)&1 (b0/b1), e=j&1 ; k = kt*16+2*tg+rr*8+e
#define WF_QKV 0
#define WF_O   110592
#define WF_M1  147456
#define WF_M2  294912
#define WF_TOTAL 442368
static __device__ __align__(16) __nv_bfloat16 g_wB[WF_TOTAL];

__global__ void cvt_weights(const float* __restrict__ wqkv, const float* __restrict__ wo,
                            const float* __restrict__ wm1,  const float* __restrict__ wm2)
{
    const int i = blockIdx.x * 256 + threadIdx.x;
    if (i >= WF_TOTAL) return;
    const int j    = i & 15;
    const int lane = (i >> 4) & 31;
    const int unit = i >> 9;
    const int sn = j >> 2, rr = (j >> 1) & 1, e = j & 1;
    const int gr = lane >> 2, tg = lane & 3;
    const int kk = 2 * tg + rr * 8 + e;          // k offset within kt16
    float v;
    if (i < WF_O) {                                  // qkv: S=18
        const int slab = unit % 18, kt = unit / 18;
        v = wqkv[(kt * 16 + kk) * 576 + slab * 32 + sn * 8 + gr];
    } else if (i < WF_M1) {                          // o: S=6
        const int u = unit - 216;
        const int slab = u % 6, kt = u / 6;
        v = wo[(kt * 16 + kk) * 192 + slab * 32 + sn * 8 + gr];
    } else if (i < WF_M2) {                          // m1: S=24
        const int u = unit - 288;
        const int slab = u % 24, kt = u / 24;
        v = wm1[(kt * 16 + kk) * 768 + slab * 32 + sn * 8 + gr];
    } else {                                         // m2: 4 chunks, S=6
        const int u = unit - 576;
        const int chunk = u / 72;
        const int u2 = u - chunk * 72;
        const int slab = u2 % 6, kt = u2 / 6;
        v = wm2[(chunk * 192 + kt * 16 + kk) * 192 + slab * 32 + sn * 8 + gr];
    }
    g_wB[i] = __float2bfloat16(v);
}

__device__ __forceinline__ void mma_bf16(float (&d)[4],
                                         uint32_t a0, uint32_t a1, uint32_t a2, uint32_t a3,
                                         uint32_t b0, uint32_t b1)
{
    asm volatile(
        "mma.sync.aligned.m16n8k16.row.col.f32.bf16.bf16.f32 "
        "{%0,%1,%2,%3}, {%4,%5,%6,%7}, {%8,%9}, {%0,%1,%2,%3};"
        : "+f"(d[0]), "+f"(d[1]), "+f"(d[2]), "+f"(d[3])
        : "r"(a0), "r"(a1), "r"(a2), "r"(a3), "r"(b0), "r"(b1));
}

__device__ __forceinline__ uint32_t packbf(float x, float y)
{
    __nv_bfloat162 h = __floats2bfloat162_rn(x, y);
    return *(uint32_t*)&h;
}

__device__ __forceinline__ int permL(int l) { return l ^ ((l >> 3) & 3); }

// word index (fp32/uint32 slot) of bf16 PAIR (t, c even) in an A-frag slab
__device__ __forceinline__ int fragWord(int slab, int t, int c)
{
    const int unit = (c >> 4) * 4 + (t >> 4);
    const int lane = (t & 7) * 4 + ((c >> 1) & 3);
    const int r = (((c >> 3) & 1) << 1) | ((t >> 3) & 1);
    return slab + unit * 128 + permL(lane) * 4 + r;
}

// word index of bf16 pair (channels c,c+1; c even) for K B-frag at token tok
__device__ __forceinline__ int kWord(int tok, int c)
{
    return OFF_K + ((c >> 4) * 8 + (tok >> 3)) * 64
           + ((tok & 7) * 4 + ((c >> 1) & 3)) * 2 + ((c >> 3) & 1);
}

// bf16 element index for V B-frag (k = token, col = channel)
__device__ __forceinline__ int vElem(int tok, int c)
{
    return OFF_V * 2 + ((tok >> 4) * 24 + (c >> 3)) * 128
           + ((c & 7) * 4 + ((tok >> 1) & 3)) * 4 + ((tok >> 3) & 1) * 2 + (tok & 1);
}

// acc[2][4][4] += A(bf16 frag SMEM) @ W(bf16 frag gmem); no syncs
__device__ __forceinline__ void gemm16(const float* __restrict__ sm, int slabA,
                                       const __nv_bfloat16* __restrict__ fragBase,
                                       int S, int slab,
                                       int lane, int mi,
                                       float (&acc)[2][4][4])
{
    const uint4* fp = (const uint4*)fragBase + ((size_t)slab * 32 + lane) * 2;
    const int stepU = S * 64;
    const int chunk4 = permL(lane) * 4;
    #pragma unroll 4
    for (int kt = 0; kt < 12; kt++) {
        const uint4 q0 = __ldg(fp);
        const uint4 q1 = __ldg(fp + 1);
        fp += stepU;
        #pragma unroll
        for (int s = 0; s < 2; s++) {
            const uint4 av = *(const uint4*)&sm[slabA + (kt * 4 + mi * 2 + s) * 128 + chunk4];
            mma_bf16(acc[s][0], av.x, av.y, av.z, av.w, q0.x, q0.y);
            mma_bf16(acc[s][1], av.x, av.y, av.z, av.w, q0.z, q0.w);
            mma_bf16(acc[s][2], av.x, av.y, av.z, av.w, q1.x, q1.y);
            mma_bf16(acc[s][3], av.x, av.y, av.z, av.w, q1.z, q1.w);
        }
    }
}

// token-parallel LayerNorm (fp32) over t-major src; writes fp32 t-major (optional)
// and bf16 A-frag dst
__device__ __forceinline__ void layernorm_bf(float* __restrict__ sm,
                                             int src, int dstFrag, int alsoFp32,
                                             const float* __restrict__ g,
                                             const float* __restrict__ bp,
                                             int tid)
{
    __syncthreads();
    uint32_t* smw = (uint32_t*)sm;
    const int t = tid & 63, chk = tid >> 6;
    {
        const float* row = &sm[src + t * SA + chk * 32];
        float s = 0.f, s2 = 0.f;
        #pragma unroll
        for (int j4 = 0; j4 < 8; j4++) {
            const float4 v = *(const float4*)&row[j4 * 4];
            s  += v.x + v.y + v.z + v.w;
            s2 += v.x * v.x + v.y * v.y + v.z * v.z + v.w * v.w;
        }
        sm[OFF_P + chk * 64 + t]       = s;
        sm[OFF_P + 384 + chk * 64 + t] = s2;
    }
    __syncthreads();
    if (tid < 64) {
        float s = 0.f, s2 = 0.f;
        #pragma unroll
        for (int ch = 0; ch < 6; ch++) {
            s  += sm[OFF_P + ch * 64 + tid];
            s2 += sm[OFF_P + 384 + ch * 64 + tid];
        }
        const float mean = s * (1.f / 192.f);
        const float var  = s2 * (1.f / 192.f) - mean * mean;
        sm[OFF_P + 768 + tid] = mean;
        sm[OFF_P + 832 + tid] = rsqrtf(var + 1e-5f);
    }
    __syncthreads();
    {
        const float mean = sm[OFF_P + 768 + t];
        const float rstd = sm[OFF_P + 832 + t];
        float* row = &sm[src + t * SA + chk * 32];
        #pragma unroll
        for (int j4 = 0; j4 < 8; j4++) {
            float4 v = *(const float4*)&row[j4 * 4];
            const float4 gg = *(const float4*)&g[chk * 32 + j4 * 4];
            const float4 bb = *(const float4*)&bp[chk * 32 + j4 * 4];
            v.x = (v.x - mean) * rstd * gg.x + bb.x;
            v.y = (v.y - mean) * rstd * gg.y + bb.y;
            v.z = (v.z - mean) * rstd * gg.z + bb.z;
            v.w = (v.w - mean) * rstd * gg.w + bb.w;
            if (alsoFp32) *(float4*)&row[j4 * 4] = v;
            const int c0 = chk * 32 + j4 * 4;
            smw[fragWord(dstFrag, t, c0)]     = packbf(v.x, v.y);
            smw[fragWord(dstFrag, t, c0 + 2)] = packbf(v.z, v.w);
        }
    }
    __syncthreads();
}

__global__ __launch_bounds__(384, 1)
void swin_block_kernel(const float* __restrict__ x,
                       const float* __restrict__ g1,  const float* __restrict__ b1,
                       const float* __restrict__ bqkv,
                       const float* __restrict__ bo,
                       const float* __restrict__ g2,  const float* __restrict__ b2,
                       const float* __restrict__ bm1, const float* __restrict__ bm2,
                       float* __restrict__ out)
{
    extern __shared__ float sm[];
    uint32_t* smw = (uint32_t*)sm;
    __nv_bfloat16* smb = (__nv_bfloat16*)sm;
    const int tid  = threadIdx.x;
    const int wid  = tid >> 5;
    const int lane = tid & 31;
    const int gr   = lane >> 2, tg = lane & 3;
    const int mi   = wid & 1;               // 2 m-tiles of 32 rows
    const int nj   = wid >> 1;              // 6 n-tiles of 32 cols
    const int wi   = blockIdx.x;
    const int b    = wi >> 10;
    const int hb   = (wi >> 5) & 31;
    const int wb   = wi & 31;

    // ---- gather window into X (fp32 t-major), shift folded ----
    for (int l = tid; l < 3072; l += 384) {
        const int c    = l >> 4;
        const int r16  = l & 15;
        const int ty   = r16 >> 1, half = r16 & 1;
        const int sh   = (hb * 8 + ty + 4) & 255;
        const int sw   = (wb * 8 + half * 4 + 4) & 255;
        const float4 v = *(const float4*)&x[(((size_t)(b * 192 + c)) << 16) + (sh << 8) + sw];
        const int t0 = ty * 8 + half * 4;
        sm[OFF_X + (t0 + 0) * SA + c] = v.x;
        sm[OFF_X + (t0 + 1) * SA + c] = v.y;
        sm[OFF_X + (t0 + 2) * SA + c] = v.z;
        sm[OFF_X + (t0 + 3) * SA + c] = v.w;
    }

    // ---- LN1: X -> X fp32 (residual base) + XF bf16 frag ----
    layernorm_bf(sm, OFF_X, OFF_XF, 1, g1, b1, tid);

    // ---- q / k / v GEMMs (A = XF) ----
    #pragma unroll 1
    for (int p = 0; p < 3; p++) {
        float acc[2][4][4];
        #pragma unroll
        for (int s = 0; s < 2; s++)
            #pragma unroll
            for (int n = 0; n < 4; n++)
                #pragma unroll
                for (int r = 0; r < 4; r++) acc[s][n][r] = 0.f;
        gemm16(sm, OFF_XF, g_wB + WF_QKV, 18, p * 6 + nj, lane, mi, acc);
        #pragma unroll
        for (int s = 0; s < 2; s++) {
            const int row = mi * 32 + s * 16 + gr;
            #pragma unroll
            for (int n = 0; n < 4; n++) {
                const int col = nj * 32 + n * 8 + 2 * tg;
                const float bb0 = __ldg(&bqkv[p * 192 + col]);
                const float bb1 = __ldg(&bqkv[p * 192 + col + 1]);
                const float v0 = acc[s][n][0] + bb0, v1 = acc[s][n][1] + bb1;
                const float v2 = acc[s][n][2] + bb0, v3 = acc[s][n][3] + bb1;
                if (p == 0) {
                    uint2 w; w.x = packbf(v0, v1); w.y = packbf(v2, v3);
                    *(uint2*)&smw[fragWord(OFF_QF, row, col)] = w;
                } else if (p == 1) {
                    smw[kWord(row, col)]     = packbf(v0, v1);
                    smw[kWord(row + 8, col)] = packbf(v2, v3);
                } else {
                    smb[vElem(row, col)]         = __float2bfloat16(v0);
                    smb[vElem(row, col + 1)]     = __float2bfloat16(v1);
                    smb[vElem(row + 8, col)]     = __float2bfloat16(v2);
                    smb[vElem(row + 8, col + 1)] = __float2bfloat16(v3);
                }
            }
        }
    }
    __syncthreads();

    // ---- attention: 16 warp-tasks (head h, 16-row tile mi2); ZERO barriers ----
    const float scale = 0.14433756729740643f;     // 1/sqrt(48)
    const int chunk4 = permL(lane) * 4;
    for (int task = wid; task < 16; task += 12) {
        const int h = task >> 2, mi2 = task & 3;
        float sc[8][4];
        #pragma unroll
        for (int ni = 0; ni < 8; ni++)
            #pragma unroll
            for (int r = 0; r < 4; r++) sc[ni][r] = 0.f;
        // scores: A = Q frag, B = K frag (3 kt16 over 48 channels)
        #pragma unroll
        for (int kk = 0; kk < 3; kk++) {
            const uint4 av = *(const uint4*)&sm[OFF_QF + ((h * 3 + kk) * 4 + mi2) * 128 + chunk4];
            const int kbase = OFF_K + (h * 3 + kk) * 8 * 64 + lane * 2;
            #pragma unroll
            for (int ni = 0; ni < 8; ni++) {
                const uint2 bv = *(const uint2*)&smw[kbase + ni * 64];
                mma_bf16(sc[ni], av.x, av.y, av.z, av.w, bv.x, bv.y);
            }
        }
        // in-register fp32 softmax over 64 cols
        {
            float m0 = -1e30f, m1 = -1e30f;
            #pragma unroll
            for (int ni = 0; ni < 8; ni++) {
                #pragma unroll
                for (int r = 0; r < 4; r++) sc[ni][r] *= scale;
                m0 = fmaxf(m0, fmaxf(sc[ni][0], sc[ni][1]));
                m1 = fmaxf(m1, fmaxf(sc[ni][2], sc[ni][3]));
            }
            m0 = fmaxf(m0, __shfl_xor_sync(0xffffffffu, m0, 1));
            m0 = fmaxf(m0, __shfl_xor_sync(0xffffffffu, m0, 2));
            m1 = fmaxf(m1, __shfl_xor_sync(0xffffffffu, m1, 1));
            m1 = fmaxf(m1, __shfl_xor_sync(0xffffffffu, m1, 2));
            float s0 = 0.f, s1 = 0.f;
            #pragma unroll
            for (int ni = 0; ni < 8; ni++) {
                sc[ni][0] = __expf(sc[ni][0] - m0);
                sc[ni][1] = __expf(sc[ni][1] - m0);
                sc[ni][2] = __expf(sc[ni][2] - m1);
                sc[ni][3] = __expf(sc[ni][3] - m1);
                s0 += sc[ni][0] + sc[ni][1];
                s1 += sc[ni][2] + sc[ni][3];
            }
            s0 += __shfl_xor_sync(0xffffffffu, s0, 1);
            s0 += __shfl_xor_sync(0xffffffffu, s0, 2);
            s1 += __shfl_xor_sync(0xffffffffu, s1, 1);
            s1 += __shfl_xor_sync(0xffffffffu, s1, 2);
            const float i0 = 1.f / s0, i1 = 1.f / s1;
            #pragma unroll
            for (int ni = 0; ni < 8; ni++) {
                sc[ni][0] *= i0; sc[ni][1] *= i0;
                sc[ni][2] *= i1; sc[ni][3] *= i1;
            }
        }
        // AV: A-frags packed DIRECTLY from sc (layout match); B = V frag
        {
            float ao[6][4];
            #pragma unroll
            for (int ci = 0; ci < 6; ci++)
                #pragma unroll
                for (int r = 0; r < 4; r++) ao[ci][r] = 0.f;
            #pragma unroll
            for (int c = 0; c < 4; c++) {
                const uint32_t a0 = packbf(sc[2 * c][0],     sc[2 * c][1]);
                const uint32_t a1 = packbf(sc[2 * c][2],     sc[2 * c][3]);
                const uint32_t a2 = packbf(sc[2 * c + 1][0], sc[2 * c + 1][1]);
                const uint32_t a3 = packbf(sc[2 * c + 1][2], sc[2 * c + 1][3]);
                const int vbase = OFF_V + (c * 24 + h * 6) * 64 + lane * 2;
                #pragma unroll
                for (int ci = 0; ci < 6; ci++) {
                    const uint2 bv = *(const uint2*)&smw[vbase + ci * 64];
                    mma_bf16(ao[ci], a0, a1, a2, a3, bv.x, bv.y);
                }
            }
            const int row = mi2 * 16 + gr;
            #pragma unroll
            for (int ci = 0; ci < 6; ci++) {
                const int col = h * 48 + ci * 8 + 2 * tg;
                uint2 w; w.x = packbf(ao[ci][0], ao[ci][1]); w.y = packbf(ao[ci][2], ao[ci][3]);
                *(uint2*)&smw[fragWord(OFF_QF, row, col)] = w;
            }
        }
    }
    __syncthreads();

    // ---- o-proj (A = O in QF) + residual RMW into X fp32 ----
    {
        float acc[2][4][4];
        #pragma unroll
        for (int s = 0; s < 2; s++)
            #pragma unroll
            for (int n = 0; n < 4; n++)
                #pragma unroll
                for (int r = 0; r < 4; r++) acc[s][n][r] = 0.f;
        gemm16(sm, OFF_QF, g_wB + WF_O, 6, nj, lane, mi, acc);
        #pragma unroll
        for (int s = 0; s < 2; s++) {
            const int row = mi * 32 + s * 16 + gr;
            #pragma unroll
            for (int n = 0; n < 4; n++) {
                const int col = nj * 32 + n * 8 + 2 * tg;
                const float bb0 = __ldg(&bo[col]);
                const float bb1 = __ldg(&bo[col + 1]);
                sm[OFF_X + row * SA + col]           += acc[s][n][0] + bb0;
                sm[OFF_X + row * SA + col + 1]       += acc[s][n][1] + bb1;
                sm[OFF_X + (row + 8) * SA + col]     += acc[s][n][2] + bb0;
                sm[OFF_X + (row + 8) * SA + col + 1] += acc[s][n][3] + bb1;
            }
        }
    }

    // ---- LN2: X -> H bf16 frag in QF (X stays fp32 residual) ----
    layernorm_bf(sm, OFF_X, OFF_QF, 0, g2, b2, tid);

    // ---- MLP: 4 hidden slabs of 192; G bf16 frag in XF ----
    float acc2[2][4][4];
    #pragma unroll
    for (int s = 0; s < 2; s++)
        #pragma unroll
        for (int n = 0; n < 4; n++)
            #pragma unroll
            for (int r = 0; r < 4; r++) acc2[s][n][r] = 0.f;

    #pragma unroll 1
    for (int jt = 0; jt < 4; jt++) {
        float acc1[2][4][4];
        #pragma unroll
        for (int s = 0; s < 2; s++)
            #pragma unroll
            for (int n = 0; n < 4; n++)
                #pragma unroll
                for (int r = 0; r < 4; r++) acc1[s][n][r] = 0.f;
        gemm16(sm, OFF_QF, g_wB + WF_M1, 24, jt * 6 + nj, lane, mi, acc1);
        #pragma unroll
        for (int s = 0; s < 2; s++) {
            const int row = mi * 32 + s * 16 + gr;
            #pragma unroll
            for (int n = 0; n < 4; n++) {
                const int col = nj * 32 + n * 8 + 2 * tg;
                const float bb0 = __ldg(&bm1[jt * 192 + col]);
                const float bb1 = __ldg(&bm1[jt * 192 + col + 1]);
                float v0 = acc1[s][n][0] + bb0, v1 = acc1[s][n][1] + bb1;
                float v2 = acc1[s][n][2] + bb0, v3 = acc1[s][n][3] + bb1;
                v0 = 0.5f * v0 * (1.f + erff(v0 * 0.70710678118654752f));
                v1 = 0.5f * v1 * (1.f + erff(v1 * 0.70710678118654752f));
                v2 = 0.5f * v2 * (1.f + erff(v2 * 0.70710678118654752f));
                v3 = 0.5f * v3 * (1.f + erff(v3 * 0.70710678118654752f));
                uint2 w; w.x = packbf(v0, v1); w.y = packbf(v2, v3);
                *(uint2*)&smw[fragWord(OFF_XF, row, col)] = w;
            }
        }
        __syncthreads();            // G complete before gemm2 reads it
        gemm16(sm, OFF_XF, g_wB + WF_M2 + jt * 36864, 6, nj, lane, mi, acc2);
        __syncthreads();            // G consumed before next jt overwrites
    }

    // ---- residual + staged scatter (3 chunks of 64 cols via P) ----
    {
        for (int ch = 0; ch < 3; ch++) {
            #pragma unroll
            for (int s = 0; s < 2; s++) {
                const int row = mi * 32 + s * 16 + gr;
                #pragma unroll
                for (int n = 0; n < 4; n++) {
                    const int col = nj * 32 + n * 8 + 2 * tg;
                    if ((col >> 6) == ch) {
                        const int cl = col & 63;
                        const float bb0 = __ldg(&bm2[col]);
                        const float bb1 = __ldg(&bm2[col + 1]);
                        sm[OFF_P + cl * SP + row]           = acc2[s][n][0] + bb0 + sm[OFF_X + row * SA + col];
                        sm[OFF_P + (cl + 1) * SP + row]     = acc2[s][n][1] + bb1 + sm[OFF_X + row * SA + col + 1];
                        sm[OFF_P + cl * SP + row + 8]       = acc2[s][n][2] + bb0 + sm[OFF_X + (row + 8) * SA + col];
                        sm[OFF_P + (cl + 1) * SP + row + 8] = acc2[s][n][3] + bb1 + sm[OFF_X + (row + 8) * SA + col + 1];
                    }
                }
            }
            __syncthreads();
            for (int l = tid; l < 1024; l += 384) {
                const int cl  = l >> 4;
                const int r16 = l & 15;
                const int ty  = r16 >> 1, half = r16 & 1;
                const int c   = ch * 64 + cl;
                const int sh  = (hb * 8 + ty + 4) & 255;
                const int sw  = (wb * 8 + half * 4 + 4) & 255;
                const float4 v = *(const float4*)&sm[OFF_P + cl * SP + ty * 8 + half * 4];
                *(float4*)&out[(((size_t)(b * 192 + c)) << 16) + (sh << 8) + sw] = v;
            }
            __syncthreads();
        }
    }
}

extern "C" void kernel_launch(void* const* d_in, const int* in_sizes, int n_in,
                              void* d_out, int out_size)
{
    (void)in_sizes; (void)n_in; (void)out_size;
    const float* x    = (const float*)d_in[0];
    const float* g1   = (const float*)d_in[1];
    const float* b1   = (const float*)d_in[2];
    const float* wqkv = (const float*)d_in[3];
    const float* bqkv = (const float*)d_in[4];
    const float* wo   = (const float*)d_in[5];
    const float* bo   = (const float*)d_in[6];
    const float* g2   = (const float*)d_in[7];
    const float* b2   = (const float*)d_in[8];
    const float* wm1  = (const float*)d_in[9];
    const float* bm1  = (const float*)d_in[10];
    const float* wm2  = (const float*)d_in[11];
    const float* bm2  = (const float*)d_in[12];
    float* out = (float*)d_out;

    cvt_weights<<<(WF_TOTAL + 255) / 256, 256>>>(wqkv, wo, wm1, wm2);
    cudaFuncSetAttribute(swin_block_kernel,
                         cudaFuncAttributeMaxDynamicSharedMemorySize, SMEM_BYTES);
    swin_block_kernel<<<4096, 384, SMEM_BYTES>>>(
        x, g1, b1, bqkv, bo, g2, b2, bm1, bm2, out);
}